// round 11
// baseline (speedup 1.0000x reference)
#include <cuda_runtime.h>
#include <cuda_bf16.h>
#include <math.h>
#include <stdint.h>

#define SQ   2048
#define EE   2048
#define HH   16
#define QLR  1536
#define KLR  512
#define DNN  128
#define DRR  64
#define DVV  128
#define DQQ  192
#define N1C  2176   // padded combined N for gemm1 (1536 + 576 -> 17*128)

// -------- scratch --------
__device__ float g_c1  [SQ * N1C];          // [qa(1536) | ckv(512) | kpe_raw(64) | pad]
__device__ float g_q   [SQ * HH * DQQ];

__device__ __nv_bfloat16 g_Ah [SQ * EE];
__device__ __nv_bfloat16 g_Al [SQ * EE];
__device__ __nv_bfloat16 g_Bh [QLR * 3072];
__device__ __nv_bfloat16 g_Bl [QLR * 3072];
__device__ __nv_bfloat16 g_kvh[SQ * HH * 256];
__device__ __nv_bfloat16 g_kvl[SQ * HH * 256];
__device__ __nv_bfloat16 g_kpeh[SQ * DRR];
__device__ __nv_bfloat16 g_kpel[SQ * DRR];

// ======================= helpers =======================
__device__ __forceinline__ uint32_t s2u(const void* p) {
    return (uint32_t)__cvta_generic_to_shared(p);
}
__device__ __forceinline__ void cpa(uint32_t d, const void* s) {
    asm volatile("cp.async.cg.shared.global [%0], [%1], 16;\n" :: "r"(d), "l"(s));
}
#define CP_COMMIT asm volatile("cp.async.commit_group;\n")
#define CP_WAIT0  asm volatile("cp.async.wait_group 0;\n")
#define CP_WAIT1  asm volatile("cp.async.wait_group 1;\n")
#define CP_WAIT2  asm volatile("cp.async.wait_group 2;\n")

__device__ __forceinline__ void ldsm4(uint32_t a, unsigned* d) {
    asm volatile("ldmatrix.sync.aligned.m8n8.x4.shared.b16 {%0,%1,%2,%3}, [%4];\n"
        : "=r"(d[0]), "=r"(d[1]), "=r"(d[2]), "=r"(d[3]) : "r"(a));
}
__device__ __forceinline__ void ldsm2(uint32_t a, unsigned* d) {
    asm volatile("ldmatrix.sync.aligned.m8n8.x2.shared.b16 {%0,%1}, [%2];\n"
        : "=r"(d[0]), "=r"(d[1]) : "r"(a));
}
__device__ __forceinline__ void ldsm2t(uint32_t a, unsigned* d) {
    asm volatile("ldmatrix.sync.aligned.m8n8.x2.trans.shared.b16 {%0,%1}, [%2];\n"
        : "=r"(d[0]), "=r"(d[1]) : "r"(a));
}
__device__ __forceinline__ void mma_bf16(float* d, const unsigned* a, const unsigned* b) {
    asm volatile(
        "mma.sync.aligned.m16n8k16.row.col.f32.bf16.bf16.f32 "
        "{%0,%1,%2,%3}, {%4,%5,%6,%7}, {%8,%9}, {%0,%1,%2,%3};\n"
        : "+f"(d[0]), "+f"(d[1]), "+f"(d[2]), "+f"(d[3])
        : "r"(a[0]), "r"(a[1]), "r"(a[2]), "r"(a[3]), "r"(b[0]), "r"(b[1]));
}
__device__ __forceinline__ unsigned short bfu(__nv_bfloat16 v) {
    return *(unsigned short*)&v;
}
__device__ __forceinline__ void packsplit(float x, float y, unsigned& h, unsigned& l) {
    __nv_bfloat16 xh = __float2bfloat16(x), yh = __float2bfloat16(y);
    __nv_bfloat16 xl = __float2bfloat16(x - __bfloat162float(xh));
    __nv_bfloat16 yl = __float2bfloat16(y - __bfloat162float(yh));
    h = (unsigned)bfu(xh) | ((unsigned)bfu(yh) << 16);
    l = (unsigned)bfu(xl) | ((unsigned)bfu(yl) << 16);
}
__device__ __forceinline__ void split8(const float* f, uint4& hv, uint4& lv) {
    unsigned hw[4], lw[4];
#pragma unroll
    for (int j = 0; j < 4; j++) packsplit(f[2 * j], f[2 * j + 1], hw[j], lw[j]);
    hv = make_uint4(hw[0], hw[1], hw[2], hw[3]);
    lv = make_uint4(lw[0], lw[1], lw[2], lw[3]);
}

// ======================= fp32 -> bf16 hi/lo split ===========================
__global__ void conv_split(const float* __restrict__ in,
                           __nv_bfloat16* __restrict__ hi,
                           __nv_bfloat16* __restrict__ lo, int n) {
    int i = (blockIdx.x * blockDim.x + threadIdx.x) * 8;
    if (i >= n) return;
    float f[8];
    *(float4*)&f[0] = *(const float4*)(in + i);
    *(float4*)&f[4] = *(const float4*)(in + i + 4);
    uint4 hv, lv;
    split8(f, hv, lv);
    *(uint4*)(hi + i) = hv;
    *(uint4*)(lo + i) = lv;
}

// strided-dest variant: scatter [K,Nin] into combined [K,Nstr] at colOff
__global__ void conv_splitN(const float* __restrict__ in,
                            __nv_bfloat16* __restrict__ hi,
                            __nv_bfloat16* __restrict__ lo,
                            int Nin, int colOff, int Nstr, int n) {
    int i = (blockIdx.x * blockDim.x + threadIdx.x) * 8;
    if (i >= n) return;
    int r = i / Nin, c = i % Nin;
    float f[8];
    *(float4*)&f[0] = *(const float4*)(in + i);
    *(float4*)&f[4] = *(const float4*)(in + i + 4);
    uint4 hv, lv;
    split8(f, hv, lv);
    size_t o = (size_t)r * Nstr + colOff + c;
    *(uint4*)(hi + o) = hv;
    *(uint4*)(lo + o) = lv;
}

// ======================= RMSNorm fused with split ===========================
__global__ void rmsnorm_split(const float* __restrict__ in,
                              const float* __restrict__ w,
                              __nv_bfloat16* __restrict__ hi,
                              __nv_bfloat16* __restrict__ lo,
                              int D, int in_stride) {
    const int row = blockIdx.x;
    const float* x = in + (size_t)row * in_stride;
    float ss = 0.f;
    for (int i = threadIdx.x; i < D; i += blockDim.x) { float v = x[i]; ss += v * v; }
#pragma unroll
    for (int m = 16; m; m >>= 1) ss += __shfl_xor_sync(0xffffffffu, ss, m);
    __shared__ float wsum[8];
    if ((threadIdx.x & 31) == 0) wsum[threadIdx.x >> 5] = ss;
    __syncthreads();
    float tot = 0.f;
#pragma unroll
    for (int i = 0; i < 8; i++) tot += wsum[i];
    float scale = rsqrtf(tot / (float)D + 1e-6f);
    for (int i = threadIdx.x; i < D; i += blockDim.x) {
        float v = x[i] * scale * w[i];
        __nv_bfloat16 h = __float2bfloat16(v);
        __nv_bfloat16 l = __float2bfloat16(v - __bfloat162float(h));
        hi[(size_t)row * D + i] = h;
        lo[(size_t)row * D + i] = l;
    }
}

// ======================= bgemm2: cross-barrier fragment preload =============
// Step s body: load_stage(s+2) -> MMA(kk0, preloaded) -> LDSM(kk16) ->
// MMA(kk16) -> wait(stage s+1) -> __syncthreads -> LDSM preload (s+1, kk0).
// Memory-model: every smem READ happens after (all threads' wait + barrier)
// for that stage. load_stage(s+2) overwrites buf (s-1)%3 whose last readers
// (step s-1 body + its tail preload of buf s%3? no — body reads only) all
// precede step s-1's tail barrier.
#define BG_STAGE 32768
#define BG_SMEM  (3 * BG_STAGE)

__global__ __launch_bounds__(256, 2) void bgemm2(const __nv_bfloat16* __restrict__ Ahg,
                                                 const __nv_bfloat16* __restrict__ Alg,
                                                 const __nv_bfloat16* __restrict__ Bhg,
                                                 const __nv_bfloat16* __restrict__ Blg,
                                                 float* __restrict__ C,
                                                 __nv_bfloat16* __restrict__ Ch,
                                                 __nv_bfloat16* __restrict__ Cl,
                                                 int N, int K, int mode) {
    extern __shared__ char smem[];
    const uint32_t sb = s2u(smem);
    const int tid = threadIdx.x;
    const int lane = tid & 31, warp = tid >> 5;
    const int wm = warp >> 2, wn = warp & 3;
    const int g = lane >> 2, t = lane & 3;
    const int bm = blockIdx.y * 128, bn = blockIdx.x * 128;
    const int lr = (lane & 7) + 8 * ((lane >> 3) & 1);

    float acc[4][4][4];
#pragma unroll
    for (int mt = 0; mt < 4; mt++)
#pragma unroll
        for (int nt = 0; nt < 4; nt++)
#pragma unroll
            for (int k = 0; k < 4; k++) acc[mt][nt][k] = 0.f;

    const int nsteps = K >> 5;

    auto load_stage = [&](int s) {
        uint32_t base = sb + (s % 3) * BG_STAGE;
        int k0 = s << 5;
#pragma unroll
        for (int p = 0; p < 2; p++) {
            int id = tid + p * 256;
            int r = id >> 2, sg = id & 3;
            uint32_t dst = base + r * 64 + (((sg ^ ((r >> 1) & 3))) << 4);
            size_t go = (size_t)(bm + r) * K + k0 + sg * 8;
            cpa(dst, Ahg + go);
            cpa(dst + 8192, Alg + go);
        }
#pragma unroll
        for (int p = 0; p < 2; p++) {
            int id = tid + p * 256;
            int r = id >> 4, sg = id & 15;
            uint32_t dst = base + 16384 + r * 256 + ((sg ^ (r & 7)) << 4);
            size_t go = (size_t)(k0 + r) * N + bn + sg * 8;
            cpa(dst, Bhg + go);
            cpa(dst + 8192, Blg + go);
        }
        CP_COMMIT;
    };

    unsigned ah[4][4], al[4][4], bh[4][2], bl[4][2];

    auto load_frags = [&](uint32_t ab, uint32_t bb, int kk) {
        int sgA = (kk >> 3) + (lane >> 4);
#pragma unroll
        for (int mt = 0; mt < 4; mt++) {
            int row = wm * 64 + mt * 16 + lr;
            uint32_t a = ab + row * 64 + ((sgA ^ ((row >> 1) & 3)) << 4);
            ldsm4(a, ah[mt]);
            ldsm4(a + 8192, al[mt]);
        }
        int rB = kk + lr;
#pragma unroll
        for (int nt = 0; nt < 4; nt++) {
            int sgB = wn * 4 + nt;
            uint32_t b = bb + rB * 256 + ((sgB ^ (rB & 7)) << 4);
            ldsm2t(b, bh[nt]);
            ldsm2t(b + 8192, bl[nt]);
        }
    };
    auto mma_frags = [&]() {
#pragma unroll
        for (int mt = 0; mt < 4; mt++)
#pragma unroll
            for (int nt = 0; nt < 4; nt++) {
                mma_bf16(acc[mt][nt], ah[mt], bh[nt]);
                mma_bf16(acc[mt][nt], ah[mt], bl[nt]);
                mma_bf16(acc[mt][nt], al[mt], bh[nt]);
            }
    };

    load_stage(0);
    if (nsteps > 1) load_stage(1);
    // prologue: stage 0 landed (all threads) -> preload its kk=0 fragments
    if (nsteps > 1) { CP_WAIT1; } else { CP_WAIT0; }
    __syncthreads();
    load_frags(sb, sb + 16384, 0);

    for (int s = 0; s < nsteps; s++) {
        if (s + 2 < nsteps) load_stage(s + 2);   // writes buf (s-1)%3 (readers done)

        uint32_t ab = sb + (s % 3) * BG_STAGE;
        uint32_t bb = ab + 16384;

        mma_frags();                              // kk = 0 (preloaded)
        load_frags(ab, bb, 16);                   // overlaps kk0 MMAs
        mma_frags();                              // kk = 16

        if (s + 1 < nsteps) {
            if (s + 2 < nsteps) { CP_WAIT1; } else { CP_WAIT0; }
            __syncthreads();                      // stage s+1 visible to ALL
            uint32_t ab2 = sb + ((s + 1) % 3) * BG_STAGE;
            load_frags(ab2, ab2 + 16384, 0);      // preload next step's kk0
        }
    }

    if (mode == 0) {
#pragma unroll
        for (int mt = 0; mt < 4; mt++) {
            int row = bm + wm * 64 + mt * 16 + g;
#pragma unroll
            for (int nt = 0; nt < 4; nt++) {
                int col = bn + wn * 32 + nt * 8 + 2 * t;
                if (col < N) {
                    *(float2*)&C[(size_t)row * N + col] =
                        make_float2(acc[mt][nt][0], acc[mt][nt][1]);
                    *(float2*)&C[(size_t)(row + 8) * N + col] =
                        make_float2(acc[mt][nt][2], acc[mt][nt][3]);
                }
            }
        }
    } else {
#pragma unroll
        for (int mt = 0; mt < 4; mt++) {
            int row = bm + wm * 64 + mt * 16 + g;
#pragma unroll
            for (int nt = 0; nt < 4; nt++) {
                int col = bn + wn * 32 + nt * 8 + 2 * t;
                unsigned hw, lw;
                packsplit(acc[mt][nt][0], acc[mt][nt][1], hw, lw);
                *(unsigned*)(Ch + (size_t)row * N + col) = hw;
                *(unsigned*)(Cl + (size_t)row * N + col) = lw;
                packsplit(acc[mt][nt][2], acc[mt][nt][3], hw, lw);
                *(unsigned*)(Ch + (size_t)(row + 8) * N + col) = hw;
                *(unsigned*)(Cl + (size_t)(row + 8) * N + col) = lw;
            }
        }
    }
}

// ======================= RoPE-K (reads combined c1) ========================
#define LOG2_10000_OVER_32 0.4152410118609203f

__global__ void rope_k_split(const float* __restrict__ src, int stride,
                             __nv_bfloat16* __restrict__ kpeh,
                             __nv_bfloat16* __restrict__ kpel) {
    int w = (blockIdx.x * blockDim.x + threadIdx.x) >> 5;
    int lane = threadIdx.x & 31;
    if (w >= SQ) return;
    const float* base = src + (size_t)w * stride;
    float x0 = base[2 * lane];
    float x1 = base[2 * lane + 1];
    float invf = exp2f(-(float)lane * LOG2_10000_OVER_32);
    float ang = (float)w * invf;
    float sn, cs;
    sincosf(ang, &sn, &cs);
    float o0 = x0 * cs - x1 * sn;
    float o1 = x1 * cs + x0 * sn;
    __nv_bfloat16 h0 = __float2bfloat16(o0);
    __nv_bfloat16 h1 = __float2bfloat16(o1);
    kpeh[(size_t)w * DRR + lane]      = h0;
    kpeh[(size_t)w * DRR + 32 + lane] = h1;
    kpel[(size_t)w * DRR + lane]      = __float2bfloat16(o0 - __bfloat162float(h0));
    kpel[(size_t)w * DRR + 32 + lane] = __float2bfloat16(o1 - __bfloat162float(h1));
}

// ======================= flash2: tensor-core flash attention ================
// BM=128, BN=64. Q rope fused at load. K double-buffered prefetch, V deferred.
#define OQH 0
#define OQL 49152
#define OKB(b) (98304 + (b) * 49152)
#define OVH 196608
#define OVL 212992
#define FL2_SMEM 229376

__global__ __launch_bounds__(256, 1) void flash2(const float* __restrict__ q,
                                                 const __nv_bfloat16* __restrict__ kvh,
                                                 const __nv_bfloat16* __restrict__ kvl,
                                                 const __nv_bfloat16* __restrict__ kpeh,
                                                 const __nv_bfloat16* __restrict__ kpel,
                                                 __nv_bfloat16* __restrict__ Oh,
                                                 __nv_bfloat16* __restrict__ Ol) {
    extern __shared__ char smem[];
    const uint32_t sb = s2u(smem);
    const int tid = threadIdx.x, lane = tid & 31, warp = tid >> 5;
    const int g = lane >> 2, t = lane & 3;
    const int h = blockIdx.y;
    const int qb = gridDim.x - 1 - blockIdx.x;
    const int q0 = qb * 128;
    const int r0 = warp * 16;
    const float scale = 0.07216878364870322f;

    auto load_K = [&](int k0, int buf) {
        uint32_t kb_h = sb + OKB(buf);
        uint32_t kb_l = kb_h + 24576;
        for (int i = tid; i < 64 * 24; i += 256) {
            int r = i / 24, sg = i % 24;
            uint32_t off = r * 384 + ((sg ^ (r & 7)) << 4);
            if (sg < 16) {
                size_t go = (size_t)(k0 + r) * (HH * 256) + h * 256 + sg * 8;
                cpa(kb_h + off, kvh + go);
                cpa(kb_l + off, kvl + go);
            } else {
                size_t go = (size_t)(k0 + r) * DRR + (sg - 16) * 8;
                cpa(kb_h + off, kpeh + go);
                cpa(kb_l + off, kpel + go);
            }
        }
        CP_COMMIT;
    };
    auto load_V = [&](int k0) {
        for (int i = tid; i < 64 * 16; i += 256) {
            int r = i / 16, sg = i % 16;
            uint32_t off = r * 256 + ((sg ^ (r & 7)) << 4);
            size_t go = (size_t)(k0 + r) * (HH * 256) + h * 256 + DNN + sg * 8;
            cpa(sb + OVH + off, kvh + go);
            cpa(sb + OVL + off, kvl + go);
        }
        CP_COMMIT;
    };

    // prefetch K[0]
    load_K(0, 0);

    // ---- Q load with fused RoPE + split ----
    for (int i = tid; i < 128 * 24; i += 256) {
        int r = i / 24, sg = i % 24;
        int qrow = q0 + r;
        const float* qr = q + (size_t)qrow * (HH * DQQ) + h * DQQ;
        float f[8];
        if (sg < 16) {
            *(float4*)&f[0] = *(const float4*)(qr + sg * 8);
            *(float4*)&f[4] = *(const float4*)(qr + sg * 8 + 4);
        } else {
            int u_base = (sg - 16) * 8;
            int j_base = u_base & 31;
            float f2[16];
            const float* pe = qr + DNN + 2 * j_base;
#pragma unroll
            for (int v = 0; v < 4; v++) *(float4*)&f2[4 * v] = *(const float4*)(pe + 4 * v);
#pragma unroll
            for (int j2 = 0; j2 < 8; j2++) {
                int j = j_base + j2;
                float x0 = f2[2 * j2], x1 = f2[2 * j2 + 1];
                float invf = exp2f(-(float)j * LOG2_10000_OVER_32);
                float sn, cs;
                sincosf((float)qrow * invf, &sn, &cs);
                f[j2] = (u_base < 32) ? (x0 * cs - x1 * sn) : (x1 * cs + x0 * sn);
            }
        }
        uint4 hv, lv;
        split8(f, hv, lv);
        uint32_t off = r * 384 + ((sg ^ (r & 7)) << 4);
        *(uint4*)(smem + OQH + off) = hv;
        *(uint4*)(smem + OQL + off) = lv;
    }

    float m0 = -1e30f, m1 = -1e30f, l0 = 0.f, l1 = 0.f;
    float oacc[16][4];
#pragma unroll
    for (int nv = 0; nv < 16; nv++)
#pragma unroll
        for (int k = 0; k < 4; k++) oacc[nv][k] = 0.f;

    const int nkb = 2 * qb + 2;
    for (int kb = 0; kb < nkb; kb++) {
        const int k0 = kb * 64;
        const int cur = kb & 1;
        const bool pre = (kb + 1 < nkb);
        __syncthreads();
        load_V(k0);
        if (pre) load_K(k0 + 64, cur ^ 1);
        if (pre) { CP_WAIT2; } else { CP_WAIT1; }
        __syncthreads();

        // S = Q @ K^T
        float sacc[8][4];
#pragma unroll
        for (int nt = 0; nt < 8; nt++)
#pragma unroll
            for (int k = 0; k < 4; k++) sacc[nt][k] = 0.f;

        const uint32_t kb_h = sb + OKB(cur);
        const int lr = (lane & 7) + 8 * ((lane >> 3) & 1);
#pragma unroll
        for (int kk = 0; kk < 192; kk += 16) {
            unsigned ah[4], al[4];
            int rowA = r0 + lr;
            int sgA = (kk >> 3) + (lane >> 4);
            uint32_t a = sb + OQH + rowA * 384 + ((sgA ^ (rowA & 7)) << 4);
            ldsm4(a, ah);
            ldsm4(a + (OQL - OQH), al);
            int sgB = (kk >> 3) + ((lane >> 3) & 1);
#pragma unroll
            for (int nt = 0; nt < 8; nt++) {
                unsigned bh[2], bl[2];
                int rB = nt * 8 + (lane & 7);
                uint32_t b = kb_h + rB * 384 + ((sgB ^ (rB & 7)) << 4);
                ldsm2(b, bh);
                ldsm2(b + 24576, bl);
                mma_bf16(sacc[nt], ah, bh);
                mma_bf16(sacc[nt], ah, bl);
                mma_bf16(sacc[nt], al, bh);
            }
        }

        // mask + online softmax
        const int qi0 = q0 + r0 + g;
        const int qi1 = qi0 + 8;
        const bool full = (k0 + 63 <= q0 + r0);
        float mx0 = -1e30f, mx1 = -1e30f;
#pragma unroll
        for (int nt = 0; nt < 8; nt++) {
            int c = k0 + nt * 8 + 2 * t;
            float s00 = sacc[nt][0] * scale, s01 = sacc[nt][1] * scale;
            float s10 = sacc[nt][2] * scale, s11 = sacc[nt][3] * scale;
            if (!full) {
                if (c > qi0)     s00 = -1e30f;
                if (c + 1 > qi0) s01 = -1e30f;
                if (c > qi1)     s10 = -1e30f;
                if (c + 1 > qi1) s11 = -1e30f;
            }
            sacc[nt][0] = s00; sacc[nt][1] = s01;
            sacc[nt][2] = s10; sacc[nt][3] = s11;
            mx0 = fmaxf(mx0, fmaxf(s00, s01));
            mx1 = fmaxf(mx1, fmaxf(s10, s11));
        }
        mx0 = fmaxf(mx0, __shfl_xor_sync(0xffffffffu, mx0, 1));
        mx0 = fmaxf(mx0, __shfl_xor_sync(0xffffffffu, mx0, 2));
        mx1 = fmaxf(mx1, __shfl_xor_sync(0xffffffffu, mx1, 1));
        mx1 = fmaxf(mx1, __shfl_xor_sync(0xffffffffu, mx1, 2));

        float mn0 = fmaxf(m0, mx0), mn1 = fmaxf(m1, mx1);
        float a0 = __expf(m0 - mn0), a1 = __expf(m1 - mn1);
        float s0 = 0.f, s1 = 0.f;
#pragma unroll
        for (int nt = 0; nt < 8; nt++) {
            float p00 = __expf(sacc[nt][0] - mn0);
            float p01 = __expf(sacc[nt][1] - mn0);
            float p10 = __expf(sacc[nt][2] - mn1);
            float p11 = __expf(sacc[nt][3] - mn1);
            sacc[nt][0] = p00; sacc[nt][1] = p01;
            sacc[nt][2] = p10; sacc[nt][3] = p11;
            s0 += p00 + p01;
            s1 += p10 + p11;
        }
        s0 += __shfl_xor_sync(0xffffffffu, s0, 1);
        s0 += __shfl_xor_sync(0xffffffffu, s0, 2);
        s1 += __shfl_xor_sync(0xffffffffu, s1, 1);
        s1 += __shfl_xor_sync(0xffffffffu, s1, 2);
        l0 = l0 * a0 + s0;
        l1 = l1 * a1 + s1;
        m0 = mn0; m1 = mn1;
#pragma unroll
        for (int nv = 0; nv < 16; nv++) {
            oacc[nv][0] *= a0; oacc[nv][1] *= a0;
            oacc[nv][2] *= a1; oacc[nv][3] *= a1;
        }

        if (pre) { CP_WAIT1; } else { CP_WAIT0; }
        __syncthreads();

        // O += P @ V
#pragma unroll
        for (int u = 0; u < 4; u++) {
            unsigned pah[4], pal[4];
            packsplit(sacc[2 * u][0],     sacc[2 * u][1],     pah[0], pal[0]);
            packsplit(sacc[2 * u][2],     sacc[2 * u][3],     pah[1], pal[1]);
            packsplit(sacc[2 * u + 1][0], sacc[2 * u + 1][1], pah[2], pal[2]);
            packsplit(sacc[2 * u + 1][2], sacc[2 * u + 1][3], pah[3], pal[3]);
            int rV = u * 16 + lr;
#pragma unroll
            for (int nv = 0; nv < 16; nv++) {
                unsigned bvh[2], bvl[2];
                uint32_t a = sb + OVH + rV * 256 + ((nv ^ (rV & 7)) << 4);
                ldsm2t(a, bvh);
                ldsm2t(a + (OVL - OVH), bvl);
                mma_bf16(oacc[nv], pah, bvh);
                mma_bf16(oacc[nv], pah, bvl);
                mma_bf16(oacc[nv], pal, bvh);
            }
        }
    }

    // epilogue: normalize + split (feeds out-proj GEMM)
    float i0 = 1.f / l0, i1 = 1.f / l1;
    int row0 = q0 + r0 + g;
#pragma unroll
    for (int nv = 0; nv < 16; nv++) {
        int col = h * DVV + nv * 8 + 2 * t;
        unsigned hw, lw;
        packsplit(oacc[nv][0] * i0, oacc[nv][1] * i0, hw, lw);
        *(unsigned*)(Oh + (size_t)row0 * (HH * DVV) + col) = hw;
        *(unsigned*)(Ol + (size_t)row0 * (HH * DVV) + col) = lw;
        packsplit(oacc[nv][2] * i1, oacc[nv][3] * i1, hw, lw);
        *(unsigned*)(Oh + (size_t)(row0 + 8) * (HH * DVV) + col) = hw;
        *(unsigned*)(Ol + (size_t)(row0 + 8) * (HH * DVV) + col) = lw;
    }
}

// ======================= launch =======================
extern "C" void kernel_launch(void* const* d_in, const int* in_sizes, int n_in,
                              void* d_out, int out_size) {
    const float* x       = (const float*)d_in[0];
    const float* w_q_a   = (const float*)d_in[1];
    const float* q_a_ln  = (const float*)d_in[2];
    const float* w_q_b   = (const float*)d_in[3];
    const float* w_kv_a  = (const float*)d_in[4];
    const float* kv_a_ln = (const float*)d_in[5];
    const float* w_kv_b  = (const float*)d_in[6];
    const float* w_out   = (const float*)d_in[7];
    float* out = (float*)d_out;

    float *c1, *qbuf;
    __nv_bfloat16 *Ah, *Al, *Bh, *Bl, *kvh, *kvl, *kpeh, *kpel;
    cudaGetSymbolAddress((void**)&c1,   g_c1);
    cudaGetSymbolAddress((void**)&qbuf, g_q);
    cudaGetSymbolAddress((void**)&Ah,   g_Ah);
    cudaGetSymbolAddress((void**)&Al,   g_Al);
    cudaGetSymbolAddress((void**)&Bh,   g_Bh);
    cudaGetSymbolAddress((void**)&Bl,   g_Bl);
    cudaGetSymbolAddress((void**)&kvh,  g_kvh);
    cudaGetSymbolAddress((void**)&kvl,  g_kvl);
    cudaGetSymbolAddress((void**)&kpeh, g_kpeh);
    cudaGetSymbolAddress((void**)&kpel, g_kpel);

    cudaFuncSetAttribute(bgemm2, cudaFuncAttributeMaxDynamicSharedMemorySize, BG_SMEM);
    cudaFuncSetAttribute(flash2, cudaFuncAttributeMaxDynamicSharedMemorySize, FL2_SMEM);

    dim3 blk(256);
    auto conv = [&](const float* src, __nv_bfloat16* h, __nv_bfloat16* l, int n) {
        conv_split<<<(n / 8 + 255) / 256, blk>>>(src, h, l, n);
    };
    auto gemm = [&](float* c, int N, int K) {
        bgemm2<<<dim3((N + 127) / 128, SQ / 128), blk, BG_SMEM>>>(
            Ah, Al, Bh, Bl, c, nullptr, nullptr, N, K, 0);
    };

    // x -> Ah/Al
    conv(x, Ah, Al, SQ * EE);

    // merged gemm1: [x @ w_q_a | x @ w_kv_a] -> c1 [2048, 2176]
    conv_splitN<<<(EE * QLR / 8 + 255) / 256, blk>>>(w_q_a, Bh, Bl, QLR, 0, N1C, EE * QLR);
    conv_splitN<<<(EE * (KLR + DRR) / 8 + 255) / 256, blk>>>(
        w_kv_a, Bh, Bl, KLR + DRR, QLR, N1C, EE * (KLR + DRR));
    gemm(c1, N1C, EE);

    // rope k (cols 2048..2111 of c1)
    rope_k_split<<<(SQ * 32 + 255) / 256, blk>>>(c1 + QLR + KLR, N1C, kpeh, kpel);

    // rmsnorm(qa) -> Ah/Al ; q = qa_n @ w_q_b
    rmsnorm_split<<<SQ, blk>>>(c1, q_a_ln, Ah, Al, QLR, N1C);
    conv(w_q_b, Bh, Bl, QLR * HH * DQQ);
    gemm(qbuf, HH * DQQ, QLR);

    // rmsnorm(ckv) -> Ah/Al ; kv = ckv_n @ w_kv_b (split epilogue)
    rmsnorm_split<<<SQ, blk>>>(c1 + QLR, kv_a_ln, Ah, Al, KLR, N1C);
    conv(w_kv_b, Bh, Bl, KLR * HH * 256);
    bgemm2<<<dim3((HH * 256) / 128, SQ / 128), blk, BG_SMEM>>>(
        Ah, Al, Bh, Bl, nullptr, kvh, kvl, HH * 256, KLR, 1);

    // attention (rope_q fused) -> split O into Ah/Al
    flash2<<<dim3(SQ / 128, HH), blk, FL2_SMEM>>>(qbuf, kvh, kvl, kpeh, kpel, Ah, Al);

    // out = o @ w_out
    conv(w_out, Bh, Bl, HH * DVV * EE);
    gemm(out, EE, HH * DVV);
}

// round 12
// speedup vs baseline: 1.1729x; 1.1729x over previous
#include <cuda_runtime.h>
#include <cuda_bf16.h>
#include <math.h>
#include <stdint.h>

#define SQ   2048
#define EE   2048
#define HH   16
#define QLR  1536
#define KLR  512
#define DNN  128
#define DRR  64
#define DVV  128
#define DQQ  192
#define N1C  2176   // padded combined N for gemm1 (1536 + 576 -> 17*128)

// -------- scratch --------
__device__ float g_c1  [SQ * N1C];          // [qa(1536) | ckv(512) | kpe_raw(64) | pad]
__device__ float g_q   [SQ * HH * DQQ];

__device__ __nv_bfloat16 g_Ah [SQ * EE];
__device__ __nv_bfloat16 g_Al [SQ * EE];
__device__ __nv_bfloat16 g_Bh [QLR * 3072];
__device__ __nv_bfloat16 g_Bl [QLR * 3072];
__device__ __nv_bfloat16 g_kvh[SQ * HH * 256];
__device__ __nv_bfloat16 g_kvl[SQ * HH * 256];
__device__ __nv_bfloat16 g_kpeh[SQ * DRR];
__device__ __nv_bfloat16 g_kpel[SQ * DRR];

// ======================= helpers =======================
__device__ __forceinline__ uint32_t s2u(const void* p) {
    return (uint32_t)__cvta_generic_to_shared(p);
}
__device__ __forceinline__ void cpa(uint32_t d, const void* s) {
    asm volatile("cp.async.cg.shared.global [%0], [%1], 16;\n" :: "r"(d), "l"(s));
}
#define CP_COMMIT asm volatile("cp.async.commit_group;\n")
#define CP_WAIT0  asm volatile("cp.async.wait_group 0;\n")
#define CP_WAIT1  asm volatile("cp.async.wait_group 1;\n")
#define CP_WAIT2  asm volatile("cp.async.wait_group 2;\n")

__device__ __forceinline__ void ldsm4(uint32_t a, unsigned* d) {
    asm volatile("ldmatrix.sync.aligned.m8n8.x4.shared.b16 {%0,%1,%2,%3}, [%4];\n"
        : "=r"(d[0]), "=r"(d[1]), "=r"(d[2]), "=r"(d[3]) : "r"(a));
}
__device__ __forceinline__ void ldsm4t(uint32_t a, unsigned* d) {
    asm volatile("ldmatrix.sync.aligned.m8n8.x4.trans.shared.b16 {%0,%1,%2,%3}, [%4];\n"
        : "=r"(d[0]), "=r"(d[1]), "=r"(d[2]), "=r"(d[3]) : "r"(a));
}
__device__ __forceinline__ void mma_bf16(float* d, const unsigned* a, const unsigned* b) {
    asm volatile(
        "mma.sync.aligned.m16n8k16.row.col.f32.bf16.bf16.f32 "
        "{%0,%1,%2,%3}, {%4,%5,%6,%7}, {%8,%9}, {%0,%1,%2,%3};\n"
        : "+f"(d[0]), "+f"(d[1]), "+f"(d[2]), "+f"(d[3])
        : "r"(a[0]), "r"(a[1]), "r"(a[2]), "r"(a[3]), "r"(b[0]), "r"(b[1]));
}
__device__ __forceinline__ unsigned short bfu(__nv_bfloat16 v) {
    return *(unsigned short*)&v;
}
__device__ __forceinline__ void packsplit(float x, float y, unsigned& h, unsigned& l) {
    __nv_bfloat16 xh = __float2bfloat16(x), yh = __float2bfloat16(y);
    __nv_bfloat16 xl = __float2bfloat16(x - __bfloat162float(xh));
    __nv_bfloat16 yl = __float2bfloat16(y - __bfloat162float(yh));
    h = (unsigned)bfu(xh) | ((unsigned)bfu(yh) << 16);
    l = (unsigned)bfu(xl) | ((unsigned)bfu(yl) << 16);
}
__device__ __forceinline__ void split8(const float* f, uint4& hv, uint4& lv) {
    unsigned hw[4], lw[4];
#pragma unroll
    for (int j = 0; j < 4; j++) packsplit(f[2 * j], f[2 * j + 1], hw[j], lw[j]);
    hv = make_uint4(hw[0], hw[1], hw[2], hw[3]);
    lv = make_uint4(lw[0], lw[1], lw[2], lw[3]);
}

// ======================= fp32 -> bf16 hi/lo split ===========================
__global__ void conv_split(const float* __restrict__ in,
                           __nv_bfloat16* __restrict__ hi,
                           __nv_bfloat16* __restrict__ lo, int n) {
    int i = (blockIdx.x * blockDim.x + threadIdx.x) * 8;
    if (i >= n) return;
    float f[8];
    *(float4*)&f[0] = *(const float4*)(in + i);
    *(float4*)&f[4] = *(const float4*)(in + i + 4);
    uint4 hv, lv;
    split8(f, hv, lv);
    *(uint4*)(hi + i) = hv;
    *(uint4*)(lo + i) = lv;
}

// strided-dest variant: scatter [K,Nin] into combined [K,Nstr] at colOff
__global__ void conv_splitN(const float* __restrict__ in,
                            __nv_bfloat16* __restrict__ hi,
                            __nv_bfloat16* __restrict__ lo,
                            int Nin, int colOff, int Nstr, int n) {
    int i = (blockIdx.x * blockDim.x + threadIdx.x) * 8;
    if (i >= n) return;
    int r = i / Nin, c = i % Nin;
    float f[8];
    *(float4*)&f[0] = *(const float4*)(in + i);
    *(float4*)&f[4] = *(const float4*)(in + i + 4);
    uint4 hv, lv;
    split8(f, hv, lv);
    size_t o = (size_t)r * Nstr + colOff + c;
    *(uint4*)(hi + o) = hv;
    *(uint4*)(lo + o) = lv;
}

// ======================= RMSNorm fused with split ===========================
__global__ void rmsnorm_split(const float* __restrict__ in,
                              const float* __restrict__ w,
                              __nv_bfloat16* __restrict__ hi,
                              __nv_bfloat16* __restrict__ lo,
                              int D, int in_stride) {
    const int row = blockIdx.x;
    const float* x = in + (size_t)row * in_stride;
    float ss = 0.f;
    for (int i = threadIdx.x; i < D; i += blockDim.x) { float v = x[i]; ss += v * v; }
#pragma unroll
    for (int m = 16; m; m >>= 1) ss += __shfl_xor_sync(0xffffffffu, ss, m);
    __shared__ float wsum[8];
    if ((threadIdx.x & 31) == 0) wsum[threadIdx.x >> 5] = ss;
    __syncthreads();
    float tot = 0.f;
#pragma unroll
    for (int i = 0; i < 8; i++) tot += wsum[i];
    float scale = rsqrtf(tot / (float)D + 1e-6f);
    for (int i = threadIdx.x; i < D; i += blockDim.x) {
        float v = x[i] * scale * w[i];
        __nv_bfloat16 h = __float2bfloat16(v);
        __nv_bfloat16 l = __float2bfloat16(v - __bfloat162float(h));
        hi[(size_t)row * D + i] = h;
        lo[(size_t)row * D + i] = l;
    }
}

// ======================= bgemm2: 3-stage, single-barrier (R8 structure) =====
// step s: wait(stage s landed for this thread); __syncthreads (all threads);
// prefetch(s+2) [overwrites buf (s-1)%3, readers done]; compute(s).
// B fragments fetched pairwise via ldsm4t (lanes 16-31 -> next n-tile).
#define BG_STAGE 32768
#define BG_SMEM  (3 * BG_STAGE)

__global__ __launch_bounds__(256, 2) void bgemm2(const __nv_bfloat16* __restrict__ Ahg,
                                                 const __nv_bfloat16* __restrict__ Alg,
                                                 const __nv_bfloat16* __restrict__ Bhg,
                                                 const __nv_bfloat16* __restrict__ Blg,
                                                 float* __restrict__ C,
                                                 __nv_bfloat16* __restrict__ Ch,
                                                 __nv_bfloat16* __restrict__ Cl,
                                                 int N, int K, int mode) {
    extern __shared__ char smem[];
    const uint32_t sb = s2u(smem);
    const int tid = threadIdx.x;
    const int lane = tid & 31, warp = tid >> 5;
    const int wm = warp >> 2, wn = warp & 3;
    const int g = lane >> 2, t = lane & 3;
    const int bm = blockIdx.y * 128, bn = blockIdx.x * 128;

    float acc[4][4][4];
#pragma unroll
    for (int mt = 0; mt < 4; mt++)
#pragma unroll
        for (int nt = 0; nt < 4; nt++)
#pragma unroll
            for (int k = 0; k < 4; k++) acc[mt][nt][k] = 0.f;

    const int nsteps = K >> 5;

    auto load_stage = [&](int s) {
        uint32_t base = sb + (s % 3) * BG_STAGE;
        int k0 = s << 5;
#pragma unroll
        for (int p = 0; p < 2; p++) {
            int id = tid + p * 256;
            int r = id >> 2, sg = id & 3;
            uint32_t dst = base + r * 64 + (((sg ^ ((r >> 1) & 3))) << 4);
            size_t go = (size_t)(bm + r) * K + k0 + sg * 8;
            cpa(dst, Ahg + go);
            cpa(dst + 8192, Alg + go);
        }
#pragma unroll
        for (int p = 0; p < 2; p++) {
            int id = tid + p * 256;
            int r = id >> 4, sg = id & 15;
            uint32_t dst = base + 16384 + r * 256 + ((sg ^ (r & 7)) << 4);
            size_t go = (size_t)(k0 + r) * N + bn + sg * 8;
            cpa(dst, Bhg + go);
            cpa(dst + 8192, Blg + go);
        }
        CP_COMMIT;
    };

    load_stage(0);
    if (nsteps > 1) load_stage(1);

    for (int s = 0; s < nsteps; s++) {
        if (s + 1 < nsteps) { CP_WAIT1; } else { CP_WAIT0; }
        __syncthreads();
        if (s + 2 < nsteps) load_stage(s + 2);

        uint32_t ab = sb + (s % 3) * BG_STAGE;
        uint32_t bb = ab + 16384;
        const int lr = (lane & 7) + 8 * ((lane >> 3) & 1);

#pragma unroll
        for (int kk = 0; kk < 32; kk += 16) {
            unsigned ah[4][4], al[4][4], bh[4][2], bl[4][2];
            int sgA = (kk >> 3) + (lane >> 4);
#pragma unroll
            for (int mt = 0; mt < 4; mt++) {
                int row = wm * 64 + mt * 16 + lr;
                uint32_t a = ab + row * 64 + ((sgA ^ ((row >> 1) & 3)) << 4);
                ldsm4(a, ah[mt]);
                ldsm4(a + 8192, al[mt]);
            }
            // B: pairwise ldsm4t (lanes 16-31 fetch the next n-tile's column group)
            int rB = kk + lr;                       // same rows for lanes 16-31
#pragma unroll
            for (int ntp = 0; ntp < 2; ntp++) {
                int sgB = wn * 4 + 2 * ntp + (lane >> 4);
                uint32_t b = bb + rB * 256 + ((sgB ^ (rB & 7)) << 4);
                unsigned t4[4];
                ldsm4t(b, t4);
                bh[2 * ntp][0] = t4[0]; bh[2 * ntp][1] = t4[1];
                bh[2 * ntp + 1][0] = t4[2]; bh[2 * ntp + 1][1] = t4[3];
                ldsm4t(b + 8192, t4);
                bl[2 * ntp][0] = t4[0]; bl[2 * ntp][1] = t4[1];
                bl[2 * ntp + 1][0] = t4[2]; bl[2 * ntp + 1][1] = t4[3];
            }
#pragma unroll
            for (int mt = 0; mt < 4; mt++)
#pragma unroll
                for (int nt = 0; nt < 4; nt++) {
                    mma_bf16(acc[mt][nt], ah[mt], bh[nt]);
                    mma_bf16(acc[mt][nt], ah[mt], bl[nt]);
                    mma_bf16(acc[mt][nt], al[mt], bh[nt]);
                }
        }
    }

    if (mode == 0) {
#pragma unroll
        for (int mt = 0; mt < 4; mt++) {
            int row = bm + wm * 64 + mt * 16 + g;
#pragma unroll
            for (int nt = 0; nt < 4; nt++) {
                int col = bn + wn * 32 + nt * 8 + 2 * t;
                if (col < N) {
                    *(float2*)&C[(size_t)row * N + col] =
                        make_float2(acc[mt][nt][0], acc[mt][nt][1]);
                    *(float2*)&C[(size_t)(row + 8) * N + col] =
                        make_float2(acc[mt][nt][2], acc[mt][nt][3]);
                }
            }
        }
    } else {
#pragma unroll
        for (int mt = 0; mt < 4; mt++) {
            int row = bm + wm * 64 + mt * 16 + g;
#pragma unroll
            for (int nt = 0; nt < 4; nt++) {
                int col = bn + wn * 32 + nt * 8 + 2 * t;
                unsigned hw, lw;
                packsplit(acc[mt][nt][0], acc[mt][nt][1], hw, lw);
                *(unsigned*)(Ch + (size_t)row * N + col) = hw;
                *(unsigned*)(Cl + (size_t)row * N + col) = lw;
                packsplit(acc[mt][nt][2], acc[mt][nt][3], hw, lw);
                *(unsigned*)(Ch + (size_t)(row + 8) * N + col) = hw;
                *(unsigned*)(Cl + (size_t)(row + 8) * N + col) = lw;
            }
        }
    }
}

// ======================= RoPE-K (reads combined c1) ========================
#define LOG2_10000_OVER_32 0.4152410118609203f

__global__ void rope_k_split(const float* __restrict__ src, int stride,
                             __nv_bfloat16* __restrict__ kpeh,
                             __nv_bfloat16* __restrict__ kpel) {
    int w = (blockIdx.x * blockDim.x + threadIdx.x) >> 5;
    int lane = threadIdx.x & 31;
    if (w >= SQ) return;
    const float* base = src + (size_t)w * stride;
    float x0 = base[2 * lane];
    float x1 = base[2 * lane + 1];
    float invf = exp2f(-(float)lane * LOG2_10000_OVER_32);
    float ang = (float)w * invf;
    float sn, cs;
    sincosf(ang, &sn, &cs);
    float o0 = x0 * cs - x1 * sn;
    float o1 = x1 * cs + x0 * sn;
    __nv_bfloat16 h0 = __float2bfloat16(o0);
    __nv_bfloat16 h1 = __float2bfloat16(o1);
    kpeh[(size_t)w * DRR + lane]      = h0;
    kpeh[(size_t)w * DRR + 32 + lane] = h1;
    kpel[(size_t)w * DRR + lane]      = __float2bfloat16(o0 - __bfloat162float(h0));
    kpel[(size_t)w * DRR + 32 + lane] = __float2bfloat16(o1 - __bfloat162float(h1));
}

// ======================= flash2: tensor-core flash attention ================
// BM=128, BN=64. Q rope fused at load. K double-buffered prefetch, V deferred.
// K(S-phase) and V(PV-phase) fragments fetched pairwise via ldmatrix.x4.
#define OQH 0
#define OQL 49152
#define OKB(b) (98304 + (b) * 49152)
#define OVH 196608
#define OVL 212992
#define FL2_SMEM 229376

__global__ __launch_bounds__(256, 1) void flash2(const float* __restrict__ q,
                                                 const __nv_bfloat16* __restrict__ kvh,
                                                 const __nv_bfloat16* __restrict__ kvl,
                                                 const __nv_bfloat16* __restrict__ kpeh,
                                                 const __nv_bfloat16* __restrict__ kpel,
                                                 __nv_bfloat16* __restrict__ Oh,
                                                 __nv_bfloat16* __restrict__ Ol) {
    extern __shared__ char smem[];
    const uint32_t sb = s2u(smem);
    const int tid = threadIdx.x, lane = tid & 31, warp = tid >> 5;
    const int g = lane >> 2, t = lane & 3;
    const int h = blockIdx.y;
    const int qb = gridDim.x - 1 - blockIdx.x;
    const int q0 = qb * 128;
    const int r0 = warp * 16;
    const float scale = 0.07216878364870322f;

    auto load_K = [&](int k0, int buf) {
        uint32_t kb_h = sb + OKB(buf);
        uint32_t kb_l = kb_h + 24576;
        for (int i = tid; i < 64 * 24; i += 256) {
            int r = i / 24, sg = i % 24;
            uint32_t off = r * 384 + ((sg ^ (r & 7)) << 4);
            if (sg < 16) {
                size_t go = (size_t)(k0 + r) * (HH * 256) + h * 256 + sg * 8;
                cpa(kb_h + off, kvh + go);
                cpa(kb_l + off, kvl + go);
            } else {
                size_t go = (size_t)(k0 + r) * DRR + (sg - 16) * 8;
                cpa(kb_h + off, kpeh + go);
                cpa(kb_l + off, kpel + go);
            }
        }
        CP_COMMIT;
    };
    auto load_V = [&](int k0) {
        for (int i = tid; i < 64 * 16; i += 256) {
            int r = i / 16, sg = i % 16;
            uint32_t off = r * 256 + ((sg ^ (r & 7)) << 4);
            size_t go = (size_t)(k0 + r) * (HH * 256) + h * 256 + DNN + sg * 8;
            cpa(sb + OVH + off, kvh + go);
            cpa(sb + OVL + off, kvl + go);
        }
        CP_COMMIT;
    };

    // prefetch K[0]
    load_K(0, 0);

    // ---- Q load with fused RoPE + split ----
    for (int i = tid; i < 128 * 24; i += 256) {
        int r = i / 24, sg = i % 24;
        int qrow = q0 + r;
        const float* qr = q + (size_t)qrow * (HH * DQQ) + h * DQQ;
        float f[8];
        if (sg < 16) {
            *(float4*)&f[0] = *(const float4*)(qr + sg * 8);
            *(float4*)&f[4] = *(const float4*)(qr + sg * 8 + 4);
        } else {
            int u_base = (sg - 16) * 8;
            int j_base = u_base & 31;
            float f2[16];
            const float* pe = qr + DNN + 2 * j_base;
#pragma unroll
            for (int v = 0; v < 4; v++) *(float4*)&f2[4 * v] = *(const float4*)(pe + 4 * v);
#pragma unroll
            for (int j2 = 0; j2 < 8; j2++) {
                int j = j_base + j2;
                float x0 = f2[2 * j2], x1 = f2[2 * j2 + 1];
                float invf = exp2f(-(float)j * LOG2_10000_OVER_32);
                float sn, cs;
                sincosf((float)qrow * invf, &sn, &cs);
                f[j2] = (u_base < 32) ? (x0 * cs - x1 * sn) : (x1 * cs + x0 * sn);
            }
        }
        uint4 hv, lv;
        split8(f, hv, lv);
        uint32_t off = r * 384 + ((sg ^ (r & 7)) << 4);
        *(uint4*)(smem + OQH + off) = hv;
        *(uint4*)(smem + OQL + off) = lv;
    }

    float m0 = -1e30f, m1 = -1e30f, l0 = 0.f, l1 = 0.f;
    float oacc[16][4];
#pragma unroll
    for (int nv = 0; nv < 16; nv++)
#pragma unroll
        for (int k = 0; k < 4; k++) oacc[nv][k] = 0.f;

    const int nkb = 2 * qb + 2;
    for (int kb = 0; kb < nkb; kb++) {
        const int k0 = kb * 64;
        const int cur = kb & 1;
        const bool pre = (kb + 1 < nkb);
        __syncthreads();
        load_V(k0);
        if (pre) load_K(k0 + 64, cur ^ 1);
        if (pre) { CP_WAIT2; } else { CP_WAIT1; }
        __syncthreads();

        // S = Q @ K^T
        float sacc[8][4];
#pragma unroll
        for (int nt = 0; nt < 8; nt++)
#pragma unroll
            for (int k = 0; k < 4; k++) sacc[nt][k] = 0.f;

        const uint32_t kb_h = sb + OKB(cur);
        const int lr = (lane & 7) + 8 * ((lane >> 3) & 1);
#pragma unroll
        for (int kk = 0; kk < 192; kk += 16) {
            unsigned ah[4], al[4];
            int rowA = r0 + lr;
            int sgA = (kk >> 3) + (lane >> 4);
            uint32_t a = sb + OQH + rowA * 384 + ((sgA ^ (rowA & 7)) << 4);
            ldsm4(a, ah);
            ldsm4(a + (OQL - OQH), al);
            int sgB = (kk >> 3) + ((lane >> 3) & 1);
#pragma unroll
            for (int ntp = 0; ntp < 4; ntp++) {
                // lanes 16-31 fetch token rows of n-tile 2*ntp+1
                int rB = (2 * ntp + (lane >> 4)) * 8 + (lane & 7);
                uint32_t b = kb_h + rB * 384 + ((sgB ^ (rB & 7)) << 4);
                unsigned bh4[4], bl4[4];
                ldsm4(b, bh4);
                ldsm4(b + 24576, bl4);
                mma_bf16(sacc[2 * ntp],     ah, &bh4[0]);
                mma_bf16(sacc[2 * ntp],     ah, &bl4[0]);
                mma_bf16(sacc[2 * ntp],     al, &bh4[0]);
                mma_bf16(sacc[2 * ntp + 1], ah, &bh4[2]);
                mma_bf16(sacc[2 * ntp + 1], ah, &bl4[2]);
                mma_bf16(sacc[2 * ntp + 1], al, &bh4[2]);
            }
        }

        // mask + online softmax
        const int qi0 = q0 + r0 + g;
        const int qi1 = qi0 + 8;
        const bool full = (k0 + 63 <= q0 + r0);
        float mx0 = -1e30f, mx1 = -1e30f;
#pragma unroll
        for (int nt = 0; nt < 8; nt++) {
            int c = k0 + nt * 8 + 2 * t;
            float s00 = sacc[nt][0] * scale, s01 = sacc[nt][1] * scale;
            float s10 = sacc[nt][2] * scale, s11 = sacc[nt][3] * scale;
            if (!full) {
                if (c > qi0)     s00 = -1e30f;
                if (c + 1 > qi0) s01 = -1e30f;
                if (c > qi1)     s10 = -1e30f;
                if (c + 1 > qi1) s11 = -1e30f;
            }
            sacc[nt][0] = s00; sacc[nt][1] = s01;
            sacc[nt][2] = s10; sacc[nt][3] = s11;
            mx0 = fmaxf(mx0, fmaxf(s00, s01));
            mx1 = fmaxf(mx1, fmaxf(s10, s11));
        }
        mx0 = fmaxf(mx0, __shfl_xor_sync(0xffffffffu, mx0, 1));
        mx0 = fmaxf(mx0, __shfl_xor_sync(0xffffffffu, mx0, 2));
        mx1 = fmaxf(mx1, __shfl_xor_sync(0xffffffffu, mx1, 1));
        mx1 = fmaxf(mx1, __shfl_xor_sync(0xffffffffu, mx1, 2));

        float mn0 = fmaxf(m0, mx0), mn1 = fmaxf(m1, mx1);
        float a0 = __expf(m0 - mn0), a1 = __expf(m1 - mn1);
        float s0 = 0.f, s1 = 0.f;
#pragma unroll
        for (int nt = 0; nt < 8; nt++) {
            float p00 = __expf(sacc[nt][0] - mn0);
            float p01 = __expf(sacc[nt][1] - mn0);
            float p10 = __expf(sacc[nt][2] - mn1);
            float p11 = __expf(sacc[nt][3] - mn1);
            sacc[nt][0] = p00; sacc[nt][1] = p01;
            sacc[nt][2] = p10; sacc[nt][3] = p11;
            s0 += p00 + p01;
            s1 += p10 + p11;
        }
        s0 += __shfl_xor_sync(0xffffffffu, s0, 1);
        s0 += __shfl_xor_sync(0xffffffffu, s0, 2);
        s1 += __shfl_xor_sync(0xffffffffu, s1, 1);
        s1 += __shfl_xor_sync(0xffffffffu, s1, 2);
        l0 = l0 * a0 + s0;
        l1 = l1 * a1 + s1;
        m0 = mn0; m1 = mn1;
#pragma unroll
        for (int nv = 0; nv < 16; nv++) {
            oacc[nv][0] *= a0; oacc[nv][1] *= a0;
            oacc[nv][2] *= a1; oacc[nv][3] *= a1;
        }

        if (pre) { CP_WAIT1; } else { CP_WAIT0; }
        __syncthreads();

        // O += P @ V  (V fragments pairwise via ldsm4t)
        const int lrv = (lane & 7) + 8 * ((lane >> 3) & 1);
#pragma unroll
        for (int u = 0; u < 4; u++) {
            unsigned pah[4], pal[4];
            packsplit(sacc[2 * u][0],     sacc[2 * u][1],     pah[0], pal[0]);
            packsplit(sacc[2 * u][2],     sacc[2 * u][3],     pah[1], pal[1]);
            packsplit(sacc[2 * u + 1][0], sacc[2 * u + 1][1], pah[2], pal[2]);
            packsplit(sacc[2 * u + 1][2], sacc[2 * u + 1][3], pah[3], pal[3]);
            int rV = u * 16 + lrv;                 // lanes 16-31 same rows
#pragma unroll
            for (int nvp = 0; nvp < 8; nvp++) {
                int nv0 = 2 * nvp;
                // lanes 16-31 fetch column group nv0+1
                uint32_t a = sb + OVH + rV * 256 +
                             (((nv0 + (lane >> 4)) ^ (rV & 7)) << 4);
                unsigned bvh4[4], bvl4[4];
                ldsm4t(a, bvh4);
                ldsm4t(a + (OVL - OVH), bvl4);
                mma_bf16(oacc[nv0],     pah, &bvh4[0]);
                mma_bf16(oacc[nv0],     pah, &bvl4[0]);
                mma_bf16(oacc[nv0],     pal, &bvh4[0]);
                mma_bf16(oacc[nv0 + 1], pah, &bvh4[2]);
                mma_bf16(oacc[nv0 + 1], pah, &bvl4[2]);
                mma_bf16(oacc[nv0 + 1], pal, &bvh4[2]);
            }
        }
    }

    // epilogue: normalize + split (feeds out-proj GEMM)
    float i0 = 1.f / l0, i1 = 1.f / l1;
    int row0 = q0 + r0 + g;
#pragma unroll
    for (int nv = 0; nv < 16; nv++) {
        int col = h * DVV + nv * 8 + 2 * t;
        unsigned hw, lw;
        packsplit(oacc[nv][0] * i0, oacc[nv][1] * i0, hw, lw);
        *(unsigned*)(Oh + (size_t)row0 * (HH * DVV) + col) = hw;
        *(unsigned*)(Ol + (size_t)row0 * (HH * DVV) + col) = lw;
        packsplit(oacc[nv][2] * i1, oacc[nv][3] * i1, hw, lw);
        *(unsigned*)(Oh + (size_t)(row0 + 8) * (HH * DVV) + col) = hw;
        *(unsigned*)(Ol + (size_t)(row0 + 8) * (HH * DVV) + col) = lw;
    }
}

// ======================= launch =======================
extern "C" void kernel_launch(void* const* d_in, const int* in_sizes, int n_in,
                              void* d_out, int out_size) {
    const float* x       = (const float*)d_in[0];
    const float* w_q_a   = (const float*)d_in[1];
    const float* q_a_ln  = (const float*)d_in[2];
    const float* w_q_b   = (const float*)d_in[3];
    const float* w_kv_a  = (const float*)d_in[4];
    const float* kv_a_ln = (const float*)d_in[5];
    const float* w_kv_b  = (const float*)d_in[6];
    const float* w_out   = (const float*)d_in[7];
    float* out = (float*)d_out;

    float *c1, *qbuf;
    __nv_bfloat16 *Ah, *Al, *Bh, *Bl, *kvh, *kvl, *kpeh, *kpel;
    cudaGetSymbolAddress((void**)&c1,   g_c1);
    cudaGetSymbolAddress((void**)&qbuf, g_q);
    cudaGetSymbolAddress((void**)&Ah,   g_Ah);
    cudaGetSymbolAddress((void**)&Al,   g_Al);
    cudaGetSymbolAddress((void**)&Bh,   g_Bh);
    cudaGetSymbolAddress((void**)&Bl,   g_Bl);
    cudaGetSymbolAddress((void**)&kvh,  g_kvh);
    cudaGetSymbolAddress((void**)&kvl,  g_kvl);
    cudaGetSymbolAddress((void**)&kpeh, g_kpeh);
    cudaGetSymbolAddress((void**)&kpel, g_kpel);

    cudaFuncSetAttribute(bgemm2, cudaFuncAttributeMaxDynamicSharedMemorySize, BG_SMEM);
    cudaFuncSetAttribute(flash2, cudaFuncAttributeMaxDynamicSharedMemorySize, FL2_SMEM);

    dim3 blk(256);
    auto conv = [&](const float* src, __nv_bfloat16* h, __nv_bfloat16* l, int n) {
        conv_split<<<(n / 8 + 255) / 256, blk>>>(src, h, l, n);
    };
    auto gemm = [&](float* c, int N, int K) {
        bgemm2<<<dim3((N + 127) / 128, SQ / 128), blk, BG_SMEM>>>(
            Ah, Al, Bh, Bl, c, nullptr, nullptr, N, K, 0);
    };

    // x -> Ah/Al
    conv(x, Ah, Al, SQ * EE);

    // merged gemm1: [x @ w_q_a | x @ w_kv_a] -> c1 [2048, 2176]
    conv_splitN<<<(EE * QLR / 8 + 255) / 256, blk>>>(w_q_a, Bh, Bl, QLR, 0, N1C, EE * QLR);
    conv_splitN<<<(EE * (KLR + DRR) / 8 + 255) / 256, blk>>>(
        w_kv_a, Bh, Bl, KLR + DRR, QLR, N1C, EE * (KLR + DRR));
    gemm(c1, N1C, EE);

    // rope k (cols 2048..2111 of c1)
    rope_k_split<<<(SQ * 32 + 255) / 256, blk>>>(c1 + QLR + KLR, N1C, kpeh, kpel);

    // rmsnorm(qa) -> Ah/Al ; q = qa_n @ w_q_b
    rmsnorm_split<<<SQ, blk>>>(c1, q_a_ln, Ah, Al, QLR, N1C);
    conv(w_q_b, Bh, Bl, QLR * HH * DQQ);
    gemm(qbuf, HH * DQQ, QLR);

    // rmsnorm(ckv) -> Ah/Al ; kv = ckv_n @ w_kv_b (split epilogue)
    rmsnorm_split<<<SQ, blk>>>(c1 + QLR, kv_a_ln, Ah, Al, KLR, N1C);
    conv(w_kv_b, Bh, Bl, KLR * HH * 256);
    bgemm2<<<dim3((HH * 256) / 128, SQ / 128), blk, BG_SMEM>>>(
        Ah, Al, Bh, Bl, nullptr, kvh, kvl, HH * 256, KLR, 1);

    // attention (rope_q fused) -> split O into Ah/Al
    flash2<<<dim3(SQ / 128, HH), blk, FL2_SMEM>>>(qbuf, kvh, kvl, kpeh, kpel, Ah, Al);

    // out = o @ w_out
    conv(w_out, Bh, Bl, HH * DVV * EE);
    gemm(out, EE, HH * DVV);
}

// round 13
// speedup vs baseline: 1.2123x; 1.0336x over previous
#include <cuda_runtime.h>
#include <cuda_bf16.h>
#include <math.h>
#include <stdint.h>

#define SQ   2048
#define EE   2048
#define HH   16
#define QLR  1536
#define KLR  512
#define DNN  128
#define DRR  64
#define DVV  128
#define DQQ  192
#define N1C  2176   // padded combined N for gemm1 (1536 + 576 -> 17*128)

// -------- scratch --------
__device__ float g_c1  [SQ * N1C];          // [qa(1536) | ckv(512) | kpe_raw(64) | pad]
__device__ float g_q   [SQ * HH * DQQ];

__device__ __nv_bfloat16 g_Ah [SQ * EE];
__device__ __nv_bfloat16 g_Al [SQ * EE];
__device__ __nv_bfloat16 g_Bh [QLR * 3072];
__device__ __nv_bfloat16 g_Bl [QLR * 3072];
__device__ __nv_bfloat16 g_B3h[QLR * 3072];   // w_q_b split
__device__ __nv_bfloat16 g_B3l[QLR * 3072];
__device__ __nv_bfloat16 g_B2h[KLR * HH * 256]; // w_kv_b split
__device__ __nv_bfloat16 g_B2l[KLR * HH * 256];
__device__ __nv_bfloat16 g_A2h[SQ * KLR];     // ckv_n split
__device__ __nv_bfloat16 g_A2l[SQ * KLR];
__device__ __nv_bfloat16 g_kvh[SQ * HH * 256];
__device__ __nv_bfloat16 g_kvl[SQ * HH * 256];
__device__ __nv_bfloat16 g_kpeh[SQ * DRR];
__device__ __nv_bfloat16 g_kpel[SQ * DRR];

// ======================= helpers =======================
__device__ __forceinline__ uint32_t s2u(const void* p) {
    return (uint32_t)__cvta_generic_to_shared(p);
}
__device__ __forceinline__ void cpa(uint32_t d, const void* s) {
    asm volatile("cp.async.cg.shared.global [%0], [%1], 16;\n" :: "r"(d), "l"(s));
}
#define CP_COMMIT asm volatile("cp.async.commit_group;\n")
#define CP_WAIT0  asm volatile("cp.async.wait_group 0;\n")
#define CP_WAIT1  asm volatile("cp.async.wait_group 1;\n")
#define CP_WAIT2  asm volatile("cp.async.wait_group 2;\n")

__device__ __forceinline__ void ldsm4(uint32_t a, unsigned* d) {
    asm volatile("ldmatrix.sync.aligned.m8n8.x4.shared.b16 {%0,%1,%2,%3}, [%4];\n"
        : "=r"(d[0]), "=r"(d[1]), "=r"(d[2]), "=r"(d[3]) : "r"(a));
}
__device__ __forceinline__ void ldsm4t(uint32_t a, unsigned* d) {
    asm volatile("ldmatrix.sync.aligned.m8n8.x4.trans.shared.b16 {%0,%1,%2,%3}, [%4];\n"
        : "=r"(d[0]), "=r"(d[1]), "=r"(d[2]), "=r"(d[3]) : "r"(a));
}
__device__ __forceinline__ void mma_bf16(float* d, const unsigned* a, const unsigned* b) {
    asm volatile(
        "mma.sync.aligned.m16n8k16.row.col.f32.bf16.bf16.f32 "
        "{%0,%1,%2,%3}, {%4,%5,%6,%7}, {%8,%9}, {%0,%1,%2,%3};\n"
        : "+f"(d[0]), "+f"(d[1]), "+f"(d[2]), "+f"(d[3])
        : "r"(a[0]), "r"(a[1]), "r"(a[2]), "r"(a[3]), "r"(b[0]), "r"(b[1]));
}
__device__ __forceinline__ unsigned short bfu(__nv_bfloat16 v) {
    return *(unsigned short*)&v;
}
__device__ __forceinline__ void packsplit(float x, float y, unsigned& h, unsigned& l) {
    __nv_bfloat16 xh = __float2bfloat16(x), yh = __float2bfloat16(y);
    __nv_bfloat16 xl = __float2bfloat16(x - __bfloat162float(xh));
    __nv_bfloat16 yl = __float2bfloat16(y - __bfloat162float(yh));
    h = (unsigned)bfu(xh) | ((unsigned)bfu(yh) << 16);
    l = (unsigned)bfu(xl) | ((unsigned)bfu(yl) << 16);
}
__device__ __forceinline__ void split8(const float* f, uint4& hv, uint4& lv) {
    unsigned hw[4], lw[4];
#pragma unroll
    for (int j = 0; j < 4; j++) packsplit(f[2 * j], f[2 * j + 1], hw[j], lw[j]);
    hv = make_uint4(hw[0], hw[1], hw[2], hw[3]);
    lv = make_uint4(lw[0], lw[1], lw[2], lw[3]);
}

// ======================= fp32 -> bf16 hi/lo split ===========================
__global__ void conv_split(const float* __restrict__ in,
                           __nv_bfloat16* __restrict__ hi,
                           __nv_bfloat16* __restrict__ lo, int n) {
    int i = (blockIdx.x * blockDim.x + threadIdx.x) * 8;
    if (i >= n) return;
    float f[8];
    *(float4*)&f[0] = *(const float4*)(in + i);
    *(float4*)&f[4] = *(const float4*)(in + i + 4);
    uint4 hv, lv;
    split8(f, hv, lv);
    *(uint4*)(hi + i) = hv;
    *(uint4*)(lo + i) = lv;
}

// strided-dest variant: scatter [K,Nin] into combined [K,Nstr] at colOff
__global__ void conv_splitN(const float* __restrict__ in,
                            __nv_bfloat16* __restrict__ hi,
                            __nv_bfloat16* __restrict__ lo,
                            int Nin, int colOff, int Nstr, int n) {
    int i = (blockIdx.x * blockDim.x + threadIdx.x) * 8;
    if (i >= n) return;
    int r = i / Nin, c = i % Nin;
    float f[8];
    *(float4*)&f[0] = *(const float4*)(in + i);
    *(float4*)&f[4] = *(const float4*)(in + i + 4);
    uint4 hv, lv;
    split8(f, hv, lv);
    size_t o = (size_t)r * Nstr + colOff + c;
    *(uint4*)(hi + o) = hv;
    *(uint4*)(lo + o) = lv;
}

// ======================= RMSNorm fused with split ===========================
__global__ void rmsnorm_split(const float* __restrict__ in,
                              const float* __restrict__ w,
                              __nv_bfloat16* __restrict__ hi,
                              __nv_bfloat16* __restrict__ lo,
                              int D, int in_stride) {
    const int row = blockIdx.x;
    const float* x = in + (size_t)row * in_stride;
    float ss = 0.f;
    for (int i = threadIdx.x; i < D; i += blockDim.x) { float v = x[i]; ss += v * v; }
#pragma unroll
    for (int m = 16; m; m >>= 1) ss += __shfl_xor_sync(0xffffffffu, ss, m);
    __shared__ float wsum[8];
    if ((threadIdx.x & 31) == 0) wsum[threadIdx.x >> 5] = ss;
    __syncthreads();
    float tot = 0.f;
#pragma unroll
    for (int i = 0; i < 8; i++) tot += wsum[i];
    float scale = rsqrtf(tot / (float)D + 1e-6f);
    for (int i = threadIdx.x; i < D; i += blockDim.x) {
        float v = x[i] * scale * w[i];
        __nv_bfloat16 h = __float2bfloat16(v);
        __nv_bfloat16 l = __float2bfloat16(v - __bfloat162float(h));
        hi[(size_t)row * D + i] = h;
        lo[(size_t)row * D + i] = l;
    }
}

// ======================= bgemm2: 3-stage, single-barrier ====================
#define BG_STAGE 32768
#define BG_SMEM  (3 * BG_STAGE)

__global__ __launch_bounds__(256, 2) void bgemm2(const __nv_bfloat16* __restrict__ Ahg,
                                                 const __nv_bfloat16* __restrict__ Alg,
                                                 const __nv_bfloat16* __restrict__ Bhg,
                                                 const __nv_bfloat16* __restrict__ Blg,
                                                 float* __restrict__ C,
                                                 __nv_bfloat16* __restrict__ Ch,
                                                 __nv_bfloat16* __restrict__ Cl,
                                                 int N, int K, int mode) {
    extern __shared__ char smem[];
    const uint32_t sb = s2u(smem);
    const int tid = threadIdx.x;
    const int lane = tid & 31, warp = tid >> 5;
    const int wm = warp >> 2, wn = warp & 3;
    const int g = lane >> 2, t = lane & 3;
    const int bm = blockIdx.y * 128, bn = blockIdx.x * 128;

    float acc[4][4][4];
#pragma unroll
    for (int mt = 0; mt < 4; mt++)
#pragma unroll
        for (int nt = 0; nt < 4; nt++)
#pragma unroll
            for (int k = 0; k < 4; k++) acc[mt][nt][k] = 0.f;

    const int nsteps = K >> 5;

    auto load_stage = [&](int s) {
        uint32_t base = sb + (s % 3) * BG_STAGE;
        int k0 = s << 5;
#pragma unroll
        for (int p = 0; p < 2; p++) {
            int id = tid + p * 256;
            int r = id >> 2, sg = id & 3;
            uint32_t dst = base + r * 64 + (((sg ^ ((r >> 1) & 3))) << 4);
            size_t go = (size_t)(bm + r) * K + k0 + sg * 8;
            cpa(dst, Ahg + go);
            cpa(dst + 8192, Alg + go);
        }
#pragma unroll
        for (int p = 0; p < 2; p++) {
            int id = tid + p * 256;
            int r = id >> 4, sg = id & 15;
            uint32_t dst = base + 16384 + r * 256 + ((sg ^ (r & 7)) << 4);
            size_t go = (size_t)(k0 + r) * N + bn + sg * 8;
            cpa(dst, Bhg + go);
            cpa(dst + 8192, Blg + go);
        }
        CP_COMMIT;
    };

    load_stage(0);
    if (nsteps > 1) load_stage(1);

    for (int s = 0; s < nsteps; s++) {
        if (s + 1 < nsteps) { CP_WAIT1; } else { CP_WAIT0; }
        __syncthreads();
        if (s + 2 < nsteps) load_stage(s + 2);

        uint32_t ab = sb + (s % 3) * BG_STAGE;
        uint32_t bb = ab + 16384;
        const int lr = (lane & 7) + 8 * ((lane >> 3) & 1);

#pragma unroll
        for (int kk = 0; kk < 32; kk += 16) {
            unsigned ah[4][4], al[4][4], bh[4][2], bl[4][2];
            int sgA = (kk >> 3) + (lane >> 4);
#pragma unroll
            for (int mt = 0; mt < 4; mt++) {
                int row = wm * 64 + mt * 16 + lr;
                uint32_t a = ab + row * 64 + ((sgA ^ ((row >> 1) & 3)) << 4);
                ldsm4(a, ah[mt]);
                ldsm4(a + 8192, al[mt]);
            }
            int rB = kk + lr;
#pragma unroll
            for (int ntp = 0; ntp < 2; ntp++) {
                int sgB = wn * 4 + 2 * ntp + (lane >> 4);
                uint32_t b = bb + rB * 256 + ((sgB ^ (rB & 7)) << 4);
                unsigned t4[4];
                ldsm4t(b, t4);
                bh[2 * ntp][0] = t4[0]; bh[2 * ntp][1] = t4[1];
                bh[2 * ntp + 1][0] = t4[2]; bh[2 * ntp + 1][1] = t4[3];
                ldsm4t(b + 8192, t4);
                bl[2 * ntp][0] = t4[0]; bl[2 * ntp][1] = t4[1];
                bl[2 * ntp + 1][0] = t4[2]; bl[2 * ntp + 1][1] = t4[3];
            }
#pragma unroll
            for (int mt = 0; mt < 4; mt++)
#pragma unroll
                for (int nt = 0; nt < 4; nt++) {
                    mma_bf16(acc[mt][nt], ah[mt], bh[nt]);
                    mma_bf16(acc[mt][nt], ah[mt], bl[nt]);
                    mma_bf16(acc[mt][nt], al[mt], bh[nt]);
                }
        }
    }

    if (mode == 0) {
#pragma unroll
        for (int mt = 0; mt < 4; mt++) {
            int row = bm + wm * 64 + mt * 16 + g;
#pragma unroll
            for (int nt = 0; nt < 4; nt++) {
                int col = bn + wn * 32 + nt * 8 + 2 * t;
                if (col < N) {
                    *(float2*)&C[(size_t)row * N + col] =
                        make_float2(acc[mt][nt][0], acc[mt][nt][1]);
                    *(float2*)&C[(size_t)(row + 8) * N + col] =
                        make_float2(acc[mt][nt][2], acc[mt][nt][3]);
                }
            }
        }
    } else {
#pragma unroll
        for (int mt = 0; mt < 4; mt++) {
            int row = bm + wm * 64 + mt * 16 + g;
#pragma unroll
            for (int nt = 0; nt < 4; nt++) {
                int col = bn + wn * 32 + nt * 8 + 2 * t;
                unsigned hw, lw;
                packsplit(acc[mt][nt][0], acc[mt][nt][1], hw, lw);
                *(unsigned*)(Ch + (size_t)row * N + col) = hw;
                *(unsigned*)(Cl + (size_t)row * N + col) = lw;
                packsplit(acc[mt][nt][2], acc[mt][nt][3], hw, lw);
                *(unsigned*)(Ch + (size_t)(row + 8) * N + col) = hw;
                *(unsigned*)(Cl + (size_t)(row + 8) * N + col) = lw;
            }
        }
    }
}

// ======================= RoPE-K (reads combined c1) ========================
#define LOG2_10000_OVER_32 0.4152410118609203f

__global__ void rope_k_split(const float* __restrict__ src, int stride,
                             __nv_bfloat16* __restrict__ kpeh,
                             __nv_bfloat16* __restrict__ kpel) {
    int w = (blockIdx.x * blockDim.x + threadIdx.x) >> 5;
    int lane = threadIdx.x & 31;
    if (w >= SQ) return;
    const float* base = src + (size_t)w * stride;
    float x0 = base[2 * lane];
    float x1 = base[2 * lane + 1];
    float invf = exp2f(-(float)lane * LOG2_10000_OVER_32);
    float ang = (float)w * invf;
    float sn, cs;
    sincosf(ang, &sn, &cs);
    float o0 = x0 * cs - x1 * sn;
    float o1 = x1 * cs + x0 * sn;
    __nv_bfloat16 h0 = __float2bfloat16(o0);
    __nv_bfloat16 h1 = __float2bfloat16(o1);
    kpeh[(size_t)w * DRR + lane]      = h0;
    kpeh[(size_t)w * DRR + 32 + lane] = h1;
    kpel[(size_t)w * DRR + lane]      = __float2bfloat16(o0 - __bfloat162float(h0));
    kpel[(size_t)w * DRR + 32 + lane] = __float2bfloat16(o1 - __bfloat162float(h1));
}

// ======================= flash2: tensor-core flash attention ================
#define OQH 0
#define OQL 49152
#define OKB(b) (98304 + (b) * 49152)
#define OVH 196608
#define OVL 212992
#define FL2_SMEM 229376

__global__ __launch_bounds__(256, 1) void flash2(const float* __restrict__ q,
                                                 const __nv_bfloat16* __restrict__ kvh,
                                                 const __nv_bfloat16* __restrict__ kvl,
                                                 const __nv_bfloat16* __restrict__ kpeh,
                                                 const __nv_bfloat16* __restrict__ kpel,
                                                 __nv_bfloat16* __restrict__ Oh,
                                                 __nv_bfloat16* __restrict__ Ol) {
    extern __shared__ char smem[];
    const uint32_t sb = s2u(smem);
    const int tid = threadIdx.x, lane = tid & 31, warp = tid >> 5;
    const int g = lane >> 2, t = lane & 3;
    const int h = blockIdx.y;
    const int qb = gridDim.x - 1 - blockIdx.x;
    const int q0 = qb * 128;
    const int r0 = warp * 16;
    const float scale = 0.07216878364870322f;

    auto load_K = [&](int k0, int buf) {
        uint32_t kb_h = sb + OKB(buf);
        uint32_t kb_l = kb_h + 24576;
        for (int i = tid; i < 64 * 24; i += 256) {
            int r = i / 24, sg = i % 24;
            uint32_t off = r * 384 + ((sg ^ (r & 7)) << 4);
            if (sg < 16) {
                size_t go = (size_t)(k0 + r) * (HH * 256) + h * 256 + sg * 8;
                cpa(kb_h + off, kvh + go);
                cpa(kb_l + off, kvl + go);
            } else {
                size_t go = (size_t)(k0 + r) * DRR + (sg - 16) * 8;
                cpa(kb_h + off, kpeh + go);
                cpa(kb_l + off, kpel + go);
            }
        }
        CP_COMMIT;
    };
    auto load_V = [&](int k0) {
        for (int i = tid; i < 64 * 16; i += 256) {
            int r = i / 16, sg = i % 16;
            uint32_t off = r * 256 + ((sg ^ (r & 7)) << 4);
            size_t go = (size_t)(k0 + r) * (HH * 256) + h * 256 + DNN + sg * 8;
            cpa(sb + OVH + off, kvh + go);
            cpa(sb + OVL + off, kvl + go);
        }
        CP_COMMIT;
    };

    // prefetch K[0]
    load_K(0, 0);

    // ---- Q load with fused RoPE + split ----
    for (int i = tid; i < 128 * 24; i += 256) {
        int r = i / 24, sg = i % 24;
        int qrow = q0 + r;
        const float* qr = q + (size_t)qrow * (HH * DQQ) + h * DQQ;
        float f[8];
        if (sg < 16) {
            *(float4*)&f[0] = *(const float4*)(qr + sg * 8);
            *(float4*)&f[4] = *(const float4*)(qr + sg * 8 + 4);
        } else {
            int u_base = (sg - 16) * 8;
            int j_base = u_base & 31;
            float f2[16];
            const float* pe = qr + DNN + 2 * j_base;
#pragma unroll
            for (int v = 0; v < 4; v++) *(float4*)&f2[4 * v] = *(const float4*)(pe + 4 * v);
#pragma unroll
            for (int j2 = 0; j2 < 8; j2++) {
                int j = j_base + j2;
                float x0 = f2[2 * j2], x1 = f2[2 * j2 + 1];
                float invf = exp2f(-(float)j * LOG2_10000_OVER_32);
                float sn, cs;
                sincosf((float)qrow * invf, &sn, &cs);
                f[j2] = (u_base < 32) ? (x0 * cs - x1 * sn) : (x1 * cs + x0 * sn);
            }
        }
        uint4 hv, lv;
        split8(f, hv, lv);
        uint32_t off = r * 384 + ((sg ^ (r & 7)) << 4);
        *(uint4*)(smem + OQH + off) = hv;
        *(uint4*)(smem + OQL + off) = lv;
    }

    float m0 = -1e30f, m1 = -1e30f, l0 = 0.f, l1 = 0.f;
    float oacc[16][4];
#pragma unroll
    for (int nv = 0; nv < 16; nv++)
#pragma unroll
        for (int k = 0; k < 4; k++) oacc[nv][k] = 0.f;

    const int nkb = 2 * qb + 2;
    for (int kb = 0; kb < nkb; kb++) {
        const int k0 = kb * 64;
        const int cur = kb & 1;
        const bool pre = (kb + 1 < nkb);
        __syncthreads();
        load_V(k0);
        if (pre) load_K(k0 + 64, cur ^ 1);
        if (pre) { CP_WAIT2; } else { CP_WAIT1; }
        __syncthreads();

        // S = Q @ K^T
        float sacc[8][4];
#pragma unroll
        for (int nt = 0; nt < 8; nt++)
#pragma unroll
            for (int k = 0; k < 4; k++) sacc[nt][k] = 0.f;

        const uint32_t kb_h = sb + OKB(cur);
        const int lr = (lane & 7) + 8 * ((lane >> 3) & 1);
#pragma unroll
        for (int kk = 0; kk < 192; kk += 16) {
            unsigned ah[4], al[4];
            int rowA = r0 + lr;
            int sgA = (kk >> 3) + (lane >> 4);
            uint32_t a = sb + OQH + rowA * 384 + ((sgA ^ (rowA & 7)) << 4);
            ldsm4(a, ah);
            ldsm4(a + (OQL - OQH), al);
            int sgB = (kk >> 3) + ((lane >> 3) & 1);
#pragma unroll
            for (int ntp = 0; ntp < 4; ntp++) {
                int rB = (2 * ntp + (lane >> 4)) * 8 + (lane & 7);
                uint32_t b = kb_h + rB * 384 + ((sgB ^ (rB & 7)) << 4);
                unsigned bh4[4], bl4[4];
                ldsm4(b, bh4);
                ldsm4(b + 24576, bl4);
                mma_bf16(sacc[2 * ntp],     ah, &bh4[0]);
                mma_bf16(sacc[2 * ntp],     ah, &bl4[0]);
                mma_bf16(sacc[2 * ntp],     al, &bh4[0]);
                mma_bf16(sacc[2 * ntp + 1], ah, &bh4[2]);
                mma_bf16(sacc[2 * ntp + 1], ah, &bl4[2]);
                mma_bf16(sacc[2 * ntp + 1], al, &bh4[2]);
            }
        }

        // mask + online softmax
        const int qi0 = q0 + r0 + g;
        const int qi1 = qi0 + 8;
        const bool full = (k0 + 63 <= q0 + r0);
        float mx0 = -1e30f, mx1 = -1e30f;
#pragma unroll
        for (int nt = 0; nt < 8; nt++) {
            int c = k0 + nt * 8 + 2 * t;
            float s00 = sacc[nt][0] * scale, s01 = sacc[nt][1] * scale;
            float s10 = sacc[nt][2] * scale, s11 = sacc[nt][3] * scale;
            if (!full) {
                if (c > qi0)     s00 = -1e30f;
                if (c + 1 > qi0) s01 = -1e30f;
                if (c > qi1)     s10 = -1e30f;
                if (c + 1 > qi1) s11 = -1e30f;
            }
            sacc[nt][0] = s00; sacc[nt][1] = s01;
            sacc[nt][2] = s10; sacc[nt][3] = s11;
            mx0 = fmaxf(mx0, fmaxf(s00, s01));
            mx1 = fmaxf(mx1, fmaxf(s10, s11));
        }
        mx0 = fmaxf(mx0, __shfl_xor_sync(0xffffffffu, mx0, 1));
        mx0 = fmaxf(mx0, __shfl_xor_sync(0xffffffffu, mx0, 2));
        mx1 = fmaxf(mx1, __shfl_xor_sync(0xffffffffu, mx1, 1));
        mx1 = fmaxf(mx1, __shfl_xor_sync(0xffffffffu, mx1, 2));

        float mn0 = fmaxf(m0, mx0), mn1 = fmaxf(m1, mx1);
        float a0 = __expf(m0 - mn0), a1 = __expf(m1 - mn1);
        float s0 = 0.f, s1 = 0.f;
#pragma unroll
        for (int nt = 0; nt < 8; nt++) {
            float p00 = __expf(sacc[nt][0] - mn0);
            float p01 = __expf(sacc[nt][1] - mn0);
            float p10 = __expf(sacc[nt][2] - mn1);
            float p11 = __expf(sacc[nt][3] - mn1);
            sacc[nt][0] = p00; sacc[nt][1] = p01;
            sacc[nt][2] = p10; sacc[nt][3] = p11;
            s0 += p00 + p01;
            s1 += p10 + p11;
        }
        s0 += __shfl_xor_sync(0xffffffffu, s0, 1);
        s0 += __shfl_xor_sync(0xffffffffu, s0, 2);
        s1 += __shfl_xor_sync(0xffffffffu, s1, 1);
        s1 += __shfl_xor_sync(0xffffffffu, s1, 2);
        l0 = l0 * a0 + s0;
        l1 = l1 * a1 + s1;
        m0 = mn0; m1 = mn1;
#pragma unroll
        for (int nv = 0; nv < 16; nv++) {
            oacc[nv][0] *= a0; oacc[nv][1] *= a0;
            oacc[nv][2] *= a1; oacc[nv][3] *= a1;
        }

        if (pre) { CP_WAIT1; } else { CP_WAIT0; }
        __syncthreads();

        // O += P @ V  (V fragments pairwise via ldsm4t)
        const int lrv = (lane & 7) + 8 * ((lane >> 3) & 1);
#pragma unroll
        for (int u = 0; u < 4; u++) {
            unsigned pah[4], pal[4];
            packsplit(sacc[2 * u][0],     sacc[2 * u][1],     pah[0], pal[0]);
            packsplit(sacc[2 * u][2],     sacc[2 * u][3],     pah[1], pal[1]);
            packsplit(sacc[2 * u + 1][0], sacc[2 * u + 1][1], pah[2], pal[2]);
            packsplit(sacc[2 * u + 1][2], sacc[2 * u + 1][3], pah[3], pal[3]);
            int rV = u * 16 + lrv;
#pragma unroll
            for (int nvp = 0; nvp < 8; nvp++) {
                int nv0 = 2 * nvp;
                uint32_t a = sb + OVH + rV * 256 +
                             (((nv0 + (lane >> 4)) ^ (rV & 7)) << 4);
                unsigned bvh4[4], bvl4[4];
                ldsm4t(a, bvh4);
                ldsm4t(a + (OVL - OVH), bvl4);
                mma_bf16(oacc[nv0],     pah, &bvh4[0]);
                mma_bf16(oacc[nv0],     pah, &bvl4[0]);
                mma_bf16(oacc[nv0],     pal, &bvh4[0]);
                mma_bf16(oacc[nv0 + 1], pah, &bvh4[2]);
                mma_bf16(oacc[nv0 + 1], pah, &bvl4[2]);
                mma_bf16(oacc[nv0 + 1], pal, &bvh4[2]);
            }
        }
    }

    // epilogue: normalize + split (feeds out-proj GEMM)
    float i0 = 1.f / l0, i1 = 1.f / l1;
    int row0 = q0 + r0 + g;
#pragma unroll
    for (int nv = 0; nv < 16; nv++) {
        int col = h * DVV + nv * 8 + 2 * t;
        unsigned hw, lw;
        packsplit(oacc[nv][0] * i0, oacc[nv][1] * i0, hw, lw);
        *(unsigned*)(Oh + (size_t)row0 * (HH * DVV) + col) = hw;
        *(unsigned*)(Ol + (size_t)row0 * (HH * DVV) + col) = lw;
        packsplit(oacc[nv][2] * i1, oacc[nv][3] * i1, hw, lw);
        *(unsigned*)(Oh + (size_t)(row0 + 8) * (HH * DVV) + col) = hw;
        *(unsigned*)(Ol + (size_t)(row0 + 8) * (HH * DVV) + col) = lw;
    }
}

// ======================= launch =======================
extern "C" void kernel_launch(void* const* d_in, const int* in_sizes, int n_in,
                              void* d_out, int out_size) {
    const float* x       = (const float*)d_in[0];
    const float* w_q_a   = (const float*)d_in[1];
    const float* q_a_ln  = (const float*)d_in[2];
    const float* w_q_b   = (const float*)d_in[3];
    const float* w_kv_a  = (const float*)d_in[4];
    const float* kv_a_ln = (const float*)d_in[5];
    const float* w_kv_b  = (const float*)d_in[6];
    const float* w_out   = (const float*)d_in[7];
    float* out = (float*)d_out;

    float *c1, *qbuf;
    __nv_bfloat16 *Ah, *Al, *Bh, *Bl, *B2h, *B2l, *B3h, *B3l, *A2h, *A2l;
    __nv_bfloat16 *kvh, *kvl, *kpeh, *kpel;
    cudaGetSymbolAddress((void**)&c1,   g_c1);
    cudaGetSymbolAddress((void**)&qbuf, g_q);
    cudaGetSymbolAddress((void**)&Ah,   g_Ah);
    cudaGetSymbolAddress((void**)&Al,   g_Al);
    cudaGetSymbolAddress((void**)&Bh,   g_Bh);
    cudaGetSymbolAddress((void**)&Bl,   g_Bl);
    cudaGetSymbolAddress((void**)&B2h,  g_B2h);
    cudaGetSymbolAddress((void**)&B2l,  g_B2l);
    cudaGetSymbolAddress((void**)&B3h,  g_B3h);
    cudaGetSymbolAddress((void**)&B3l,  g_B3l);
    cudaGetSymbolAddress((void**)&A2h,  g_A2h);
    cudaGetSymbolAddress((void**)&A2l,  g_A2l);
    cudaGetSymbolAddress((void**)&kvh,  g_kvh);
    cudaGetSymbolAddress((void**)&kvl,  g_kvl);
    cudaGetSymbolAddress((void**)&kpeh, g_kpeh);
    cudaGetSymbolAddress((void**)&kpel, g_kpel);

    cudaFuncSetAttribute(bgemm2, cudaFuncAttributeMaxDynamicSharedMemorySize, BG_SMEM);
    cudaFuncSetAttribute(flash2, cudaFuncAttributeMaxDynamicSharedMemorySize, FL2_SMEM);

    // side stream + fork/join events (created per call; not captured themselves)
    cudaStream_t s2;
    cudaStreamCreateWithFlags(&s2, cudaStreamNonBlocking);
    cudaEvent_t eF0, eJ0, eF1, eJ1;
    cudaEventCreateWithFlags(&eF0, cudaEventDisableTiming);
    cudaEventCreateWithFlags(&eJ0, cudaEventDisableTiming);
    cudaEventCreateWithFlags(&eF1, cudaEventDisableTiming);
    cudaEventCreateWithFlags(&eJ1, cudaEventDisableTiming);

    dim3 blk(256);
    auto conv = [&](const float* src, __nv_bfloat16* h, __nv_bfloat16* l, int n,
                    cudaStream_t st) {
        conv_split<<<(n / 8 + 255) / 256, blk, 0, st>>>(src, h, l, n);
    };

    // ---- main: x split (first node), then fork weight convs to s2 ----
    conv(x, Ah, Al, SQ * EE, 0);
    cudaEventRecord(eF0, 0);
    cudaStreamWaitEvent(s2, eF0, 0);
    conv(w_q_b, B3h, B3l, QLR * HH * DQQ, s2);
    conv(w_kv_b, B2h, B2l, KLR * HH * 256, s2);
    cudaEventRecord(eJ0, s2);

    // ---- main: gemm1 weights + gemm1 ----
    conv_splitN<<<(EE * QLR / 8 + 255) / 256, blk>>>(w_q_a, Bh, Bl, QLR, 0, N1C, EE * QLR);
    conv_splitN<<<(EE * (KLR + DRR) / 8 + 255) / 256, blk>>>(
        w_kv_a, Bh, Bl, KLR + DRR, QLR, N1C, EE * (KLR + DRR));
    bgemm2<<<dim3(N1C / 128, SQ / 128), blk, BG_SMEM>>>(
        Ah, Al, Bh, Bl, c1, nullptr, nullptr, N1C, EE, 0);

    // rope k (cols 2048..2111 of c1)
    rope_k_split<<<(SQ * 32 + 255) / 256, blk>>>(c1 + QLR + KLR, N1C, kpeh, kpel);

    // rmsnorms: qa -> Ah/Al ; ckv -> A2h/A2l
    rmsnorm_split<<<SQ, blk>>>(c1, q_a_ln, Ah, Al, QLR, N1C);
    rmsnorm_split<<<SQ, blk>>>(c1 + QLR, kv_a_ln, A2h, A2l, KLR, N1C);

    // join weight convs; fork kv gemm to s2
    cudaStreamWaitEvent(0, eJ0, 0);
    cudaEventRecord(eF1, 0);
    cudaStreamWaitEvent(s2, eF1, 0);
    bgemm2<<<dim3((HH * 256) / 128, SQ / 128), blk, BG_SMEM, s2>>>(
        A2h, A2l, B2h, B2l, nullptr, kvh, kvl, HH * 256, KLR, 1);
    cudaEventRecord(eJ1, s2);

    // main: q = qa_n @ w_q_b (concurrent with kv gemm)
    bgemm2<<<dim3((HH * DQQ) / 128, SQ / 128), blk, BG_SMEM>>>(
        Ah, Al, B3h, B3l, qbuf, nullptr, nullptr, HH * DQQ, QLR, 0);

    // main: w_out split (Bh/Bl free after gemm1)
    conv(w_out, Bh, Bl, HH * DVV * EE, 0);

    // join kv gemm, then attention
    cudaStreamWaitEvent(0, eJ1, 0);
    flash2<<<dim3(SQ / 128, HH), blk, FL2_SMEM>>>(qbuf, kvh, kvl, kpeh, kpel, Ah, Al);

    // out = o @ w_out
    bgemm2<<<dim3(EE / 128, SQ / 128), blk, BG_SMEM>>>(
        Ah, Al, Bh, Bl, out, nullptr, nullptr, EE, HH * DVV, 0);
}

// round 14
// speedup vs baseline: 1.6480x; 1.3594x over previous
#include <cuda_runtime.h>
#include <cuda_fp16.h>
#include <math.h>
#include <stdint.h>

#define SQ   2048
#define EE   2048
#define HH   16
#define QLR  1536
#define KLR  512
#define DNN  128
#define DRR  64
#define DVV  128
#define DQQ  192
#define N1C  2176

// -------- scratch --------
__device__ float g_c1  [SQ * N1C];
__device__ float g_q   [SQ * HH * DQQ];

__device__ __half g_Ah [SQ * EE];      // activation hi
__device__ __half g_Al [SQ * EE];      // activation lo
__device__ __half g_B1 [QLR * 3072];   // gemm1 B (single fp16)
__device__ __half g_B3 [QLR * 3072];   // w_q_b
__device__ __half g_B2 [KLR * HH * 256]; // w_kv_b
__device__ __half g_BO [HH * DVV * EE];  // w_out
__device__ __half g_A2h[SQ * KLR];
__device__ __half g_A2l[SQ * KLR];
__device__ __half g_kv [SQ * HH * 256];  // kv output (single fp16)
__device__ __half g_kpe[SQ * DRR];

// ======================= helpers =======================
__device__ __forceinline__ uint32_t s2u(const void* p) {
    return (uint32_t)__cvta_generic_to_shared(p);
}
__device__ __forceinline__ void cpa(uint32_t d, const void* s) {
    asm volatile("cp.async.cg.shared.global [%0], [%1], 16;\n" :: "r"(d), "l"(s));
}
#define CP_COMMIT asm volatile("cp.async.commit_group;\n")
#define CP_WAIT0  asm volatile("cp.async.wait_group 0;\n")
#define CP_WAIT1  asm volatile("cp.async.wait_group 1;\n")
#define CP_WAIT2  asm volatile("cp.async.wait_group 2;\n")

__device__ __forceinline__ void ldsm4(uint32_t a, unsigned* d) {
    asm volatile("ldmatrix.sync.aligned.m8n8.x4.shared.b16 {%0,%1,%2,%3}, [%4];\n"
        : "=r"(d[0]), "=r"(d[1]), "=r"(d[2]), "=r"(d[3]) : "r"(a));
}
__device__ __forceinline__ void ldsm4t(uint32_t a, unsigned* d) {
    asm volatile("ldmatrix.sync.aligned.m8n8.x4.trans.shared.b16 {%0,%1,%2,%3}, [%4];\n"
        : "=r"(d[0]), "=r"(d[1]), "=r"(d[2]), "=r"(d[3]) : "r"(a));
}
__device__ __forceinline__ void mma_f16(float* d, const unsigned* a, const unsigned* b) {
    asm volatile(
        "mma.sync.aligned.m16n8k16.row.col.f32.f16.f16.f32 "
        "{%0,%1,%2,%3}, {%4,%5,%6,%7}, {%8,%9}, {%0,%1,%2,%3};\n"
        : "+f"(d[0]), "+f"(d[1]), "+f"(d[2]), "+f"(d[3])
        : "r"(a[0]), "r"(a[1]), "r"(a[2]), "r"(a[3]), "r"(b[0]), "r"(b[1]));
}
__device__ __forceinline__ unsigned short hfu(__half v) {
    return *(unsigned short*)&v;
}
__device__ __forceinline__ void packsplit(float x, float y, unsigned& h, unsigned& l) {
    __half xh = __float2half(x), yh = __float2half(y);
    __half xl = __float2half(x - __half2float(xh));
    __half yl = __float2half(y - __half2float(yh));
    h = (unsigned)hfu(xh) | ((unsigned)hfu(yh) << 16);
    l = (unsigned)hfu(xl) | ((unsigned)hfu(yl) << 16);
}
__device__ __forceinline__ unsigned packh2(float x, float y) {
    __half xh = __float2half(x), yh = __float2half(y);
    return (unsigned)hfu(xh) | ((unsigned)hfu(yh) << 16);
}
__device__ __forceinline__ void split8(const float* f, uint4& hv, uint4& lv) {
    unsigned hw[4], lw[4];
#pragma unroll
    for (int j = 0; j < 4; j++) packsplit(f[2 * j], f[2 * j + 1], hw[j], lw[j]);
    hv = make_uint4(hw[0], hw[1], hw[2], hw[3]);
    lv = make_uint4(lw[0], lw[1], lw[2], lw[3]);
}

// ======================= conversions ===========================
// A side: fp32 -> fp16 hi/lo
__global__ void conv_split(const float* __restrict__ in,
                           __half* __restrict__ hi,
                           __half* __restrict__ lo, int n) {
    int i = (blockIdx.x * blockDim.x + threadIdx.x) * 8;
    if (i >= n) return;
    float f[8];
    *(float4*)&f[0] = *(const float4*)(in + i);
    *(float4*)&f[4] = *(const float4*)(in + i + 4);
    uint4 hv, lv;
    split8(f, hv, lv);
    *(uint4*)(hi + i) = hv;
    *(uint4*)(lo + i) = lv;
}
// B side: fp32 -> single fp16
__global__ void conv_single(const float* __restrict__ in,
                            __half* __restrict__ o, int n) {
    int i = (blockIdx.x * blockDim.x + threadIdx.x) * 8;
    if (i >= n) return;
    float f[8];
    *(float4*)&f[0] = *(const float4*)(in + i);
    *(float4*)&f[4] = *(const float4*)(in + i + 4);
    unsigned w[4];
#pragma unroll
    for (int j = 0; j < 4; j++) w[j] = packh2(f[2 * j], f[2 * j + 1]);
    *(uint4*)(o + i) = make_uint4(w[0], w[1], w[2], w[3]);
}
// B side scatter into combined [K, Nstr]
__global__ void conv_singleN(const float* __restrict__ in,
                             __half* __restrict__ o,
                             int Nin, int colOff, int Nstr, int n) {
    int i = (blockIdx.x * blockDim.x + threadIdx.x) * 8;
    if (i >= n) return;
    int r = i / Nin, c = i % Nin;
    float f[8];
    *(float4*)&f[0] = *(const float4*)(in + i);
    *(float4*)&f[4] = *(const float4*)(in + i + 4);
    unsigned w[4];
#pragma unroll
    for (int j = 0; j < 4; j++) w[j] = packh2(f[2 * j], f[2 * j + 1]);
    *(uint4*)(o + (size_t)r * Nstr + colOff + c) = make_uint4(w[0], w[1], w[2], w[3]);
}

// ======================= RMSNorm fused with split ===========================
__global__ void rmsnorm_split(const float* __restrict__ in,
                              const float* __restrict__ w,
                              __half* __restrict__ hi,
                              __half* __restrict__ lo,
                              int D, int in_stride) {
    const int row = blockIdx.x;
    const float* x = in + (size_t)row * in_stride;
    float ss = 0.f;
    for (int i = threadIdx.x; i < D; i += blockDim.x) { float v = x[i]; ss += v * v; }
#pragma unroll
    for (int m = 16; m; m >>= 1) ss += __shfl_xor_sync(0xffffffffu, ss, m);
    __shared__ float wsum[8];
    if ((threadIdx.x & 31) == 0) wsum[threadIdx.x >> 5] = ss;
    __syncthreads();
    float tot = 0.f;
#pragma unroll
    for (int i = 0; i < 8; i++) tot += wsum[i];
    float scale = rsqrtf(tot / (float)D + 1e-6f);
    for (int i = threadIdx.x; i < D; i += blockDim.x) {
        float v = x[i] * scale * w[i];
        __half h = __float2half(v);
        hi[(size_t)row * D + i] = h;
        lo[(size_t)row * D + i] = __float2half(v - __half2float(h));
    }
}

// ======================= bgemm2: fp16 A-x2 / B-x1 ===========================
// stage (24KB): Ah[128x32] +0, Al +8192, B[32x128] +16384
#define BG_STAGE 24576
#define BG_SMEM  (3 * BG_STAGE)

__global__ __launch_bounds__(256, 2) void bgemm2(const __half* __restrict__ Ahg,
                                                 const __half* __restrict__ Alg,
                                                 const __half* __restrict__ Bg,
                                                 float* __restrict__ C,
                                                 __half* __restrict__ Ch,
                                                 int N, int K, int mode) {
    extern __shared__ char smem[];
    const uint32_t sb = s2u(smem);
    const int tid = threadIdx.x;
    const int lane = tid & 31, warp = tid >> 5;
    const int wm = warp >> 2, wn = warp & 3;
    const int g = lane >> 2, t = lane & 3;
    const int bm = blockIdx.y * 128, bn = blockIdx.x * 128;

    float acc[4][4][4];
#pragma unroll
    for (int mt = 0; mt < 4; mt++)
#pragma unroll
        for (int nt = 0; nt < 4; nt++)
#pragma unroll
            for (int k = 0; k < 4; k++) acc[mt][nt][k] = 0.f;

    const int nsteps = K >> 5;

    auto load_stage = [&](int s) {
        uint32_t base = sb + (s % 3) * BG_STAGE;
        int k0 = s << 5;
#pragma unroll
        for (int p = 0; p < 2; p++) {
            int id = tid + p * 256;
            int r = id >> 2, sg = id & 3;
            uint32_t dst = base + r * 64 + (((sg ^ ((r >> 1) & 3))) << 4);
            size_t go = (size_t)(bm + r) * K + k0 + sg * 8;
            cpa(dst, Ahg + go);
            cpa(dst + 8192, Alg + go);
        }
#pragma unroll
        for (int p = 0; p < 2; p++) {
            int id = tid + p * 256;
            int r = id >> 4, sg = id & 15;
            uint32_t dst = base + 16384 + r * 256 + ((sg ^ (r & 7)) << 4);
            size_t go = (size_t)(k0 + r) * N + bn + sg * 8;
            cpa(dst, Bg + go);
        }
        CP_COMMIT;
    };

    load_stage(0);
    if (nsteps > 1) load_stage(1);

    for (int s = 0; s < nsteps; s++) {
        if (s + 1 < nsteps) { CP_WAIT1; } else { CP_WAIT0; }
        __syncthreads();
        if (s + 2 < nsteps) load_stage(s + 2);

        uint32_t ab = sb + (s % 3) * BG_STAGE;
        uint32_t bb = ab + 16384;
        const int lr = (lane & 7) + 8 * ((lane >> 3) & 1);

#pragma unroll
        for (int kk = 0; kk < 32; kk += 16) {
            unsigned ah[4][4], al[4][4], bf[4][2];
            int sgA = (kk >> 3) + (lane >> 4);
#pragma unroll
            for (int mt = 0; mt < 4; mt++) {
                int row = wm * 64 + mt * 16 + lr;
                uint32_t a = ab + row * 64 + ((sgA ^ ((row >> 1) & 3)) << 4);
                ldsm4(a, ah[mt]);
                ldsm4(a + 8192, al[mt]);
            }
            int rB = kk + lr;
#pragma unroll
            for (int ntp = 0; ntp < 2; ntp++) {
                int sgB = wn * 4 + 2 * ntp + (lane >> 4);
                uint32_t b = bb + rB * 256 + ((sgB ^ (rB & 7)) << 4);
                unsigned t4[4];
                ldsm4t(b, t4);
                bf[2 * ntp][0] = t4[0]; bf[2 * ntp][1] = t4[1];
                bf[2 * ntp + 1][0] = t4[2]; bf[2 * ntp + 1][1] = t4[3];
            }
#pragma unroll
            for (int mt = 0; mt < 4; mt++)
#pragma unroll
                for (int nt = 0; nt < 4; nt++) {
                    mma_f16(acc[mt][nt], ah[mt], bf[nt]);
                    mma_f16(acc[mt][nt], al[mt], bf[nt]);
                }
        }
    }

    if (mode == 0) {
#pragma unroll
        for (int mt = 0; mt < 4; mt++) {
            int row = bm + wm * 64 + mt * 16 + g;
#pragma unroll
            for (int nt = 0; nt < 4; nt++) {
                int col = bn + wn * 32 + nt * 8 + 2 * t;
                if (col < N) {
                    *(float2*)&C[(size_t)row * N + col] =
                        make_float2(acc[mt][nt][0], acc[mt][nt][1]);
                    *(float2*)&C[(size_t)(row + 8) * N + col] =
                        make_float2(acc[mt][nt][2], acc[mt][nt][3]);
                }
            }
        }
    } else {
        // single fp16 epilogue (kv buffer)
#pragma unroll
        for (int mt = 0; mt < 4; mt++) {
            int row = bm + wm * 64 + mt * 16 + g;
#pragma unroll
            for (int nt = 0; nt < 4; nt++) {
                int col = bn + wn * 32 + nt * 8 + 2 * t;
                *(unsigned*)(Ch + (size_t)row * N + col) =
                    packh2(acc[mt][nt][0], acc[mt][nt][1]);
                *(unsigned*)(Ch + (size_t)(row + 8) * N + col) =
                    packh2(acc[mt][nt][2], acc[mt][nt][3]);
            }
        }
    }
}

// ======================= RoPE-K =============================================
#define LOG2_10000_OVER_32 0.4152410118609203f

__global__ void rope_k_split(const float* __restrict__ src, int stride,
                             __half* __restrict__ kpe) {
    int w = (blockIdx.x * blockDim.x + threadIdx.x) >> 5;
    int lane = threadIdx.x & 31;
    if (w >= SQ) return;
    const float* base = src + (size_t)w * stride;
    float x0 = base[2 * lane];
    float x1 = base[2 * lane + 1];
    float invf = exp2f(-(float)lane * LOG2_10000_OVER_32);
    float ang = (float)w * invf;
    float sn, cs;
    sincosf(ang, &sn, &cs);
    kpe[(size_t)w * DRR + lane]      = __float2half(x0 * cs - x1 * sn);
    kpe[(size_t)w * DRR + 32 + lane] = __float2half(x1 * cs + x0 * sn);
}

// ======================= flash2: fp16 tensor-core flash =====================
// smem: Qh 0..48K, Ql 48K..96K, K bufs 96K + b*24K (single), V 144K..160K
#define OQH 0
#define OQL 49152
#define OKB(b) (98304 + (b) * 24576)
#define OVH 147456
#define FL2_SMEM 163840

__global__ __launch_bounds__(256, 1) void flash2(const float* __restrict__ q,
                                                 const __half* __restrict__ kv,
                                                 const __half* __restrict__ kpe,
                                                 __half* __restrict__ Oh,
                                                 __half* __restrict__ Ol) {
    extern __shared__ char smem[];
    const uint32_t sb = s2u(smem);
    const int tid = threadIdx.x, lane = tid & 31, warp = tid >> 5;
    const int g = lane >> 2, t = lane & 3;
    const int h = blockIdx.y;
    const int qb = gridDim.x - 1 - blockIdx.x;
    const int q0 = qb * 128;
    const int r0 = warp * 16;
    const float scale = 0.07216878364870322f;

    auto load_K = [&](int k0, int buf) {
        uint32_t kb = sb + OKB(buf);
        for (int i = tid; i < 64 * 24; i += 256) {
            int r = i / 24, sg = i % 24;
            uint32_t off = r * 384 + ((sg ^ (r & 7)) << 4);
            if (sg < 16) {
                cpa(kb + off, kv + (size_t)(k0 + r) * (HH * 256) + h * 256 + sg * 8);
            } else {
                cpa(kb + off, kpe + (size_t)(k0 + r) * DRR + (sg - 16) * 8);
            }
        }
        CP_COMMIT;
    };
    auto load_V = [&](int k0) {
        for (int i = tid; i < 64 * 16; i += 256) {
            int r = i / 16, sg = i % 16;
            uint32_t off = r * 256 + ((sg ^ (r & 7)) << 4);
            cpa(sb + OVH + off, kv + (size_t)(k0 + r) * (HH * 256) + h * 256 + DNN + sg * 8);
        }
        CP_COMMIT;
    };

    load_K(0, 0);

    // ---- Q load with fused RoPE + hi/lo split ----
    for (int i = tid; i < 128 * 24; i += 256) {
        int r = i / 24, sg = i % 24;
        int qrow = q0 + r;
        const float* qr = q + (size_t)qrow * (HH * DQQ) + h * DQQ;
        float f[8];
        if (sg < 16) {
            *(float4*)&f[0] = *(const float4*)(qr + sg * 8);
            *(float4*)&f[4] = *(const float4*)(qr + sg * 8 + 4);
        } else {
            int u_base = (sg - 16) * 8;
            int j_base = u_base & 31;
            float f2[16];
            const float* pe = qr + DNN + 2 * j_base;
#pragma unroll
            for (int v = 0; v < 4; v++) *(float4*)&f2[4 * v] = *(const float4*)(pe + 4 * v);
#pragma unroll
            for (int j2 = 0; j2 < 8; j2++) {
                int j = j_base + j2;
                float x0 = f2[2 * j2], x1 = f2[2 * j2 + 1];
                float invf = exp2f(-(float)j * LOG2_10000_OVER_32);
                float sn, cs;
                sincosf((float)qrow * invf, &sn, &cs);
                f[j2] = (u_base < 32) ? (x0 * cs - x1 * sn) : (x1 * cs + x0 * sn);
            }
        }
        uint4 hv, lv;
        split8(f, hv, lv);
        uint32_t off = r * 384 + ((sg ^ (r & 7)) << 4);
        *(uint4*)(smem + OQH + off) = hv;
        *(uint4*)(smem + OQL + off) = lv;
    }

    float m0 = -1e30f, m1 = -1e30f, l0 = 0.f, l1 = 0.f;
    float oacc[16][4];
#pragma unroll
    for (int nv = 0; nv < 16; nv++)
#pragma unroll
        for (int k = 0; k < 4; k++) oacc[nv][k] = 0.f;

    const int nkb = 2 * qb + 2;
    for (int kb = 0; kb < nkb; kb++) {
        const int k0 = kb * 64;
        const int cur = kb & 1;
        const bool pre = (kb + 1 < nkb);
        __syncthreads();
        load_V(k0);
        if (pre) load_K(k0 + 64, cur ^ 1);
        if (pre) { CP_WAIT2; } else { CP_WAIT1; }
        __syncthreads();

        // S = Q @ K^T
        float sacc[8][4];
#pragma unroll
        for (int nt = 0; nt < 8; nt++)
#pragma unroll
            for (int k = 0; k < 4; k++) sacc[nt][k] = 0.f;

        const uint32_t kbb = sb + OKB(cur);
        const int lr = (lane & 7) + 8 * ((lane >> 3) & 1);
#pragma unroll
        for (int kk = 0; kk < 192; kk += 16) {
            unsigned ah[4], al[4];
            int rowA = r0 + lr;
            int sgA = (kk >> 3) + (lane >> 4);
            uint32_t a = sb + OQH + rowA * 384 + ((sgA ^ (rowA & 7)) << 4);
            ldsm4(a, ah);
            ldsm4(a + (OQL - OQH), al);
            int sgB = (kk >> 3) + ((lane >> 3) & 1);
#pragma unroll
            for (int ntp = 0; ntp < 4; ntp++) {
                int rB = (2 * ntp + (lane >> 4)) * 8 + (lane & 7);
                uint32_t b = kbb + rB * 384 + ((sgB ^ (rB & 7)) << 4);
                unsigned b4[4];
                ldsm4(b, b4);
                mma_f16(sacc[2 * ntp],     ah, &b4[0]);
                mma_f16(sacc[2 * ntp],     al, &b4[0]);
                mma_f16(sacc[2 * ntp + 1], ah, &b4[2]);
                mma_f16(sacc[2 * ntp + 1], al, &b4[2]);
            }
        }

        // mask + online softmax
        const int qi0 = q0 + r0 + g;
        const int qi1 = qi0 + 8;
        const bool full = (k0 + 63 <= q0 + r0);
        float mx0 = -1e30f, mx1 = -1e30f;
#pragma unroll
        for (int nt = 0; nt < 8; nt++) {
            int c = k0 + nt * 8 + 2 * t;
            float s00 = sacc[nt][0] * scale, s01 = sacc[nt][1] * scale;
            float s10 = sacc[nt][2] * scale, s11 = sacc[nt][3] * scale;
            if (!full) {
                if (c > qi0)     s00 = -1e30f;
                if (c + 1 > qi0) s01 = -1e30f;
                if (c > qi1)     s10 = -1e30f;
                if (c + 1 > qi1) s11 = -1e30f;
            }
            sacc[nt][0] = s00; sacc[nt][1] = s01;
            sacc[nt][2] = s10; sacc[nt][3] = s11;
            mx0 = fmaxf(mx0, fmaxf(s00, s01));
            mx1 = fmaxf(mx1, fmaxf(s10, s11));
        }
        mx0 = fmaxf(mx0, __shfl_xor_sync(0xffffffffu, mx0, 1));
        mx0 = fmaxf(mx0, __shfl_xor_sync(0xffffffffu, mx0, 2));
        mx1 = fmaxf(mx1, __shfl_xor_sync(0xffffffffu, mx1, 1));
        mx1 = fmaxf(mx1, __shfl_xor_sync(0xffffffffu, mx1, 2));

        float mn0 = fmaxf(m0, mx0), mn1 = fmaxf(m1, mx1);
        float a0 = __expf(m0 - mn0), a1 = __expf(m1 - mn1);
        float s0 = 0.f, s1 = 0.f;
#pragma unroll
        for (int nt = 0; nt < 8; nt++) {
            float p00 = __expf(sacc[nt][0] - mn0);
            float p01 = __expf(sacc[nt][1] - mn0);
            float p10 = __expf(sacc[nt][2] - mn1);
            float p11 = __expf(sacc[nt][3] - mn1);
            sacc[nt][0] = p00; sacc[nt][1] = p01;
            sacc[nt][2] = p10; sacc[nt][3] = p11;
            s0 += p00 + p01;
            s1 += p10 + p11;
        }
        s0 += __shfl_xor_sync(0xffffffffu, s0, 1);
        s0 += __shfl_xor_sync(0xffffffffu, s0, 2);
        s1 += __shfl_xor_sync(0xffffffffu, s1, 1);
        s1 += __shfl_xor_sync(0xffffffffu, s1, 2);
        l0 = l0 * a0 + s0;
        l1 = l1 * a1 + s1;
        m0 = mn0; m1 = mn1;
#pragma unroll
        for (int nv = 0; nv < 16; nv++) {
            oacc[nv][0] *= a0; oacc[nv][1] *= a0;
            oacc[nv][2] *= a1; oacc[nv][3] *= a1;
        }

        if (pre) { CP_WAIT1; } else { CP_WAIT0; }
        __syncthreads();

        // O += P @ V  (P hi/lo, V single)
        const int lrv = (lane & 7) + 8 * ((lane >> 3) & 1);
#pragma unroll
        for (int u = 0; u < 4; u++) {
            unsigned pah[4], pal[4];
            packsplit(sacc[2 * u][0],     sacc[2 * u][1],     pah[0], pal[0]);
            packsplit(sacc[2 * u][2],     sacc[2 * u][3],     pah[1], pal[1]);
            packsplit(sacc[2 * u + 1][0], sacc[2 * u + 1][1], pah[2], pal[2]);
            packsplit(sacc[2 * u + 1][2], sacc[2 * u + 1][3], pah[3], pal[3]);
            int rV = u * 16 + lrv;
#pragma unroll
            for (int nvp = 0; nvp < 8; nvp++) {
                int nv0 = 2 * nvp;
                uint32_t a = sb + OVH + rV * 256 +
                             (((nv0 + (lane >> 4)) ^ (rV & 7)) << 4);
                unsigned bv4[4];
                ldsm4t(a, bv4);
                mma_f16(oacc[nv0],     pah, &bv4[0]);
                mma_f16(oacc[nv0],     pal, &bv4[0]);
                mma_f16(oacc[nv0 + 1], pah, &bv4[2]);
                mma_f16(oacc[nv0 + 1], pal, &bv4[2]);
            }
        }
    }

    // epilogue: normalize + hi/lo split (A side of out-proj)
    float i0 = 1.f / l0, i1 = 1.f / l1;
    int row0 = q0 + r0 + g;
#pragma unroll
    for (int nv = 0; nv < 16; nv++) {
        int col = h * DVV + nv * 8 + 2 * t;
        unsigned hw, lw;
        packsplit(oacc[nv][0] * i0, oacc[nv][1] * i0, hw, lw);
        *(unsigned*)(Oh + (size_t)row0 * (HH * DVV) + col) = hw;
        *(unsigned*)(Ol + (size_t)row0 * (HH * DVV) + col) = lw;
        packsplit(oacc[nv][2] * i1, oacc[nv][3] * i1, hw, lw);
        *(unsigned*)(Oh + (size_t)(row0 + 8) * (HH * DVV) + col) = hw;
        *(unsigned*)(Ol + (size_t)(row0 + 8) * (HH * DVV) + col) = lw;
    }
}

// ======================= launch =======================
extern "C" void kernel_launch(void* const* d_in, const int* in_sizes, int n_in,
                              void* d_out, int out_size) {
    const float* x       = (const float*)d_in[0];
    const float* w_q_a   = (const float*)d_in[1];
    const float* q_a_ln  = (const float*)d_in[2];
    const float* w_q_b   = (const float*)d_in[3];
    const float* w_kv_a  = (const float*)d_in[4];
    const float* kv_a_ln = (const float*)d_in[5];
    const float* w_kv_b  = (const float*)d_in[6];
    const float* w_out   = (const float*)d_in[7];
    float* out = (float*)d_out;

    float *c1, *qbuf;
    __half *Ah, *Al, *B1, *B2, *B3, *BO, *A2h, *A2l, *kv, *kpe;
    cudaGetSymbolAddress((void**)&c1,   g_c1);
    cudaGetSymbolAddress((void**)&qbuf, g_q);
    cudaGetSymbolAddress((void**)&Ah,   g_Ah);
    cudaGetSymbolAddress((void**)&Al,   g_Al);
    cudaGetSymbolAddress((void**)&B1,   g_B1);
    cudaGetSymbolAddress((void**)&B2,   g_B2);
    cudaGetSymbolAddress((void**)&B3,   g_B3);
    cudaGetSymbolAddress((void**)&BO,   g_BO);
    cudaGetSymbolAddress((void**)&A2h,  g_A2h);
    cudaGetSymbolAddress((void**)&A2l,  g_A2l);
    cudaGetSymbolAddress((void**)&kv,   g_kv);
    cudaGetSymbolAddress((void**)&kpe,  g_kpe);

    cudaFuncSetAttribute(bgemm2, cudaFuncAttributeMaxDynamicSharedMemorySize, BG_SMEM);
    cudaFuncSetAttribute(flash2, cudaFuncAttributeMaxDynamicSharedMemorySize, FL2_SMEM);

    cudaStream_t s2;
    cudaStreamCreateWithFlags(&s2, cudaStreamNonBlocking);
    cudaEvent_t eF0, eJ0, eF1, eJ1;
    cudaEventCreateWithFlags(&eF0, cudaEventDisableTiming);
    cudaEventCreateWithFlags(&eJ0, cudaEventDisableTiming);
    cudaEventCreateWithFlags(&eF1, cudaEventDisableTiming);
    cudaEventCreateWithFlags(&eJ1, cudaEventDisableTiming);

    dim3 blk(256);

    // ---- main: x split, fork weight convs to s2 ----
    conv_split<<<(SQ * EE / 8 + 255) / 256, blk>>>(x, Ah, Al, SQ * EE);
    cudaEventRecord(eF0, 0);
    cudaStreamWaitEvent(s2, eF0, 0);
    conv_single<<<(QLR * HH * DQQ / 8 + 255) / 256, blk, 0, s2>>>(w_q_b, B3, QLR * HH * DQQ);
    conv_single<<<(KLR * HH * 256 / 8 + 255) / 256, blk, 0, s2>>>(w_kv_b, B2, KLR * HH * 256);
    cudaEventRecord(eJ0, s2);

    // ---- main: gemm1 weights + gemm1 ----
    conv_singleN<<<(EE * QLR / 8 + 255) / 256, blk>>>(w_q_a, B1, QLR, 0, N1C, EE * QLR);
    conv_singleN<<<(EE * (KLR + DRR) / 8 + 255) / 256, blk>>>(
        w_kv_a, B1, KLR + DRR, QLR, N1C, EE * (KLR + DRR));
    bgemm2<<<dim3(N1C / 128, SQ / 128), blk, BG_SMEM>>>(
        Ah, Al, B1, c1, nullptr, N1C, EE, 0);

    rope_k_split<<<(SQ * 32 + 255) / 256, blk>>>(c1 + QLR + KLR, N1C, kpe);

    rmsnorm_split<<<SQ, blk>>>(c1, q_a_ln, Ah, Al, QLR, N1C);
    rmsnorm_split<<<SQ, blk>>>(c1 + QLR, kv_a_ln, A2h, A2l, KLR, N1C);

    // join weight convs; fork kv gemm to s2
    cudaStreamWaitEvent(0, eJ0, 0);
    cudaEventRecord(eF1, 0);
    cudaStreamWaitEvent(s2, eF1, 0);
    bgemm2<<<dim3((HH * 256) / 128, SQ / 128), blk, BG_SMEM, s2>>>(
        A2h, A2l, B2, nullptr, kv, HH * 256, KLR, 1);
    cudaEventRecord(eJ1, s2);

    // main: q = qa_n @ w_q_b (concurrent)
    bgemm2<<<dim3((HH * DQQ) / 128, SQ / 128), blk, BG_SMEM>>>(
        Ah, Al, B3, qbuf, nullptr, HH * DQQ, QLR, 0);

    // main: w_out single split
    conv_single<<<(HH * DVV * EE / 8 + 255) / 256, blk>>>(w_out, BO, HH * DVV * EE);

    // join kv gemm, attention
    cudaStreamWaitEvent(0, eJ1, 0);
    flash2<<<dim3(SQ / 128, HH), blk, FL2_SMEM>>>(qbuf, kv, kpe, Ah, Al);

    // out = o @ w_out
    bgemm2<<<dim3(EE / 128, SQ / 128), blk, BG_SMEM>>>(
        Ah, Al, BO, out, nullptr, EE, HH * DVV, 0);
}

// round 15
// speedup vs baseline: 1.7220x; 1.0449x over previous
#include <cuda_runtime.h>
#include <cuda_fp16.h>
#include <math.h>
#include <stdint.h>

#define SQ   2048
#define EE   2048
#define HH   16
#define QLR  1536
#define KLR  512
#define DNN  128
#define DRR  64
#define DVV  128
#define DQQ  192
#define N1C  2176

// -------- scratch --------
__device__ float g_c1  [SQ * N1C];
__device__ float g_q   [SQ * HH * DQQ];

__device__ __half g_Ah [SQ * EE];
__device__ __half g_Al [SQ * EE];
__device__ __half g_B1 [QLR * 3072];
__device__ __half g_B3 [QLR * 3072];
__device__ __half g_B2 [KLR * HH * 256];
__device__ __half g_BO [HH * DVV * EE];
__device__ __half g_A2h[SQ * KLR];
__device__ __half g_A2l[SQ * KLR];
__device__ __half g_kv [SQ * HH * 256];
__device__ __half g_kpe[SQ * DRR];

// ======================= helpers =======================
__device__ __forceinline__ uint32_t s2u(const void* p) {
    return (uint32_t)__cvta_generic_to_shared(p);
}
__device__ __forceinline__ void cpa(uint32_t d, const void* s) {
    asm volatile("cp.async.cg.shared.global [%0], [%1], 16;\n" :: "r"(d), "l"(s));
}
#define CP_COMMIT asm volatile("cp.async.commit_group;\n")
#define CP_WAIT0  asm volatile("cp.async.wait_group 0;\n")
#define CP_WAIT1  asm volatile("cp.async.wait_group 1;\n")
#define CP_WAIT2  asm volatile("cp.async.wait_group 2;\n")

__device__ __forceinline__ void ldsm4(uint32_t a, unsigned* d) {
    asm volatile("ldmatrix.sync.aligned.m8n8.x4.shared.b16 {%0,%1,%2,%3}, [%4];\n"
        : "=r"(d[0]), "=r"(d[1]), "=r"(d[2]), "=r"(d[3]) : "r"(a));
}
__device__ __forceinline__ void ldsm4t(uint32_t a, unsigned* d) {
    asm volatile("ldmatrix.sync.aligned.m8n8.x4.trans.shared.b16 {%0,%1,%2,%3}, [%4];\n"
        : "=r"(d[0]), "=r"(d[1]), "=r"(d[2]), "=r"(d[3]) : "r"(a));
}
__device__ __forceinline__ void mma_f16(float* d, const unsigned* a, const unsigned* b) {
    asm volatile(
        "mma.sync.aligned.m16n8k16.row.col.f32.f16.f16.f32 "
        "{%0,%1,%2,%3}, {%4,%5,%6,%7}, {%8,%9}, {%0,%1,%2,%3};\n"
        : "+f"(d[0]), "+f"(d[1]), "+f"(d[2]), "+f"(d[3])
        : "r"(a[0]), "r"(a[1]), "r"(a[2]), "r"(a[3]), "r"(b[0]), "r"(b[1]));
}
__device__ __forceinline__ unsigned short hfu(__half v) {
    return *(unsigned short*)&v;
}
__device__ __forceinline__ void packsplit(float x, float y, unsigned& h, unsigned& l) {
    __half xh = __float2half(x), yh = __float2half(y);
    __half xl = __float2half(x - __half2float(xh));
    __half yl = __float2half(y - __half2float(yh));
    h = (unsigned)hfu(xh) | ((unsigned)hfu(yh) << 16);
    l = (unsigned)hfu(xl) | ((unsigned)hfu(yl) << 16);
}
__device__ __forceinline__ unsigned packh2(float x, float y) {
    __half xh = __float2half(x), yh = __float2half(y);
    return (unsigned)hfu(xh) | ((unsigned)hfu(yh) << 16);
}
__device__ __forceinline__ void split8(const float* f, uint4& hv, uint4& lv) {
    unsigned hw[4], lw[4];
#pragma unroll
    for (int j = 0; j < 4; j++) packsplit(f[2 * j], f[2 * j + 1], hw[j], lw[j]);
    hv = make_uint4(hw[0], hw[1], hw[2], hw[3]);
    lv = make_uint4(lw[0], lw[1], lw[2], lw[3]);
}

// ======================= conversions ===========================
__global__ void conv_split(const float* __restrict__ in,
                           __half* __restrict__ hi,
                           __half* __restrict__ lo, int n) {
    int i = (blockIdx.x * blockDim.x + threadIdx.x) * 8;
    if (i >= n) return;
    float f[8];
    *(float4*)&f[0] = *(const float4*)(in + i);
    *(float4*)&f[4] = *(const float4*)(in + i + 4);
    uint4 hv, lv;
    split8(f, hv, lv);
    *(uint4*)(hi + i) = hv;
    *(uint4*)(lo + i) = lv;
}
__global__ void conv_single(const float* __restrict__ in,
                            __half* __restrict__ o, int n) {
    int i = (blockIdx.x * blockDim.x + threadIdx.x) * 8;
    if (i >= n) return;
    float f[8];
    *(float4*)&f[0] = *(const float4*)(in + i);
    *(float4*)&f[4] = *(const float4*)(in + i + 4);
    unsigned w[4];
#pragma unroll
    for (int j = 0; j < 4; j++) w[j] = packh2(f[2 * j], f[2 * j + 1]);
    *(uint4*)(o + i) = make_uint4(w[0], w[1], w[2], w[3]);
}
__global__ void conv_singleN(const float* __restrict__ in,
                             __half* __restrict__ o,
                             int Nin, int colOff, int Nstr, int n) {
    int i = (blockIdx.x * blockDim.x + threadIdx.x) * 8;
    if (i >= n) return;
    int r = i / Nin, c = i % Nin;
    float f[8];
    *(float4*)&f[0] = *(const float4*)(in + i);
    *(float4*)&f[4] = *(const float4*)(in + i + 4);
    unsigned w[4];
#pragma unroll
    for (int j = 0; j < 4; j++) w[j] = packh2(f[2 * j], f[2 * j + 1]);
    *(uint4*)(o + (size_t)r * Nstr + colOff + c) = make_uint4(w[0], w[1], w[2], w[3]);
}

// ======================= RMSNorm fused with split ===========================
__global__ void rmsnorm_split(const float* __restrict__ in,
                              const float* __restrict__ w,
                              __half* __restrict__ hi,
                              __half* __restrict__ lo,
                              int D, int in_stride) {
    const int row = blockIdx.x;
    const float* x = in + (size_t)row * in_stride;
    float ss = 0.f;
    for (int i = threadIdx.x; i < D; i += blockDim.x) { float v = x[i]; ss += v * v; }
#pragma unroll
    for (int m = 16; m; m >>= 1) ss += __shfl_xor_sync(0xffffffffu, ss, m);
    __shared__ float wsum[8];
    if ((threadIdx.x & 31) == 0) wsum[threadIdx.x >> 5] = ss;
    __syncthreads();
    float tot = 0.f;
#pragma unroll
    for (int i = 0; i < 8; i++) tot += wsum[i];
    float scale = rsqrtf(tot / (float)D + 1e-6f);
    for (int i = threadIdx.x; i < D; i += blockDim.x) {
        float v = x[i] * scale * w[i];
        __half h = __float2half(v);
        hi[(size_t)row * D + i] = h;
        lo[(size_t)row * D + i] = __float2half(v - __half2float(h));
    }
}

// ======================= bgemm2: fp16 A-x2 / B-x1 ===========================
#define BG_STAGE 24576
#define BG_SMEM  (3 * BG_STAGE)

__global__ __launch_bounds__(256, 2) void bgemm2(const __half* __restrict__ Ahg,
                                                 const __half* __restrict__ Alg,
                                                 const __half* __restrict__ Bg,
                                                 float* __restrict__ C,
                                                 __half* __restrict__ Ch,
                                                 int N, int K, int mode) {
    extern __shared__ char smem[];
    const uint32_t sb = s2u(smem);
    const int tid = threadIdx.x;
    const int lane = tid & 31, warp = tid >> 5;
    const int wm = warp >> 2, wn = warp & 3;
    const int g = lane >> 2, t = lane & 3;
    const int bm = blockIdx.y * 128, bn = blockIdx.x * 128;

    float acc[4][4][4];
#pragma unroll
    for (int mt = 0; mt < 4; mt++)
#pragma unroll
        for (int nt = 0; nt < 4; nt++)
#pragma unroll
            for (int k = 0; k < 4; k++) acc[mt][nt][k] = 0.f;

    const int nsteps = K >> 5;

    auto load_stage = [&](int s) {
        uint32_t base = sb + (s % 3) * BG_STAGE;
        int k0 = s << 5;
#pragma unroll
        for (int p = 0; p < 2; p++) {
            int id = tid + p * 256;
            int r = id >> 2, sg = id & 3;
            uint32_t dst = base + r * 64 + (((sg ^ ((r >> 1) & 3))) << 4);
            size_t go = (size_t)(bm + r) * K + k0 + sg * 8;
            cpa(dst, Ahg + go);
            cpa(dst + 8192, Alg + go);
        }
#pragma unroll
        for (int p = 0; p < 2; p++) {
            int id = tid + p * 256;
            int r = id >> 4, sg = id & 15;
            uint32_t dst = base + 16384 + r * 256 + ((sg ^ (r & 7)) << 4);
            size_t go = (size_t)(k0 + r) * N + bn + sg * 8;
            cpa(dst, Bg + go);
        }
        CP_COMMIT;
    };

    load_stage(0);
    if (nsteps > 1) load_stage(1);

    for (int s = 0; s < nsteps; s++) {
        if (s + 1 < nsteps) { CP_WAIT1; } else { CP_WAIT0; }
        __syncthreads();
        if (s + 2 < nsteps) load_stage(s + 2);

        uint32_t ab = sb + (s % 3) * BG_STAGE;
        uint32_t bb = ab + 16384;
        const int lr = (lane & 7) + 8 * ((lane >> 3) & 1);

#pragma unroll
        for (int kk = 0; kk < 32; kk += 16) {
            unsigned ah[4][4], al[4][4], bf[4][2];
            int sgA = (kk >> 3) + (lane >> 4);
#pragma unroll
            for (int mt = 0; mt < 4; mt++) {
                int row = wm * 64 + mt * 16 + lr;
                uint32_t a = ab + row * 64 + ((sgA ^ ((row >> 1) & 3)) << 4);
                ldsm4(a, ah[mt]);
                ldsm4(a + 8192, al[mt]);
            }
            int rB = kk + lr;
#pragma unroll
            for (int ntp = 0; ntp < 2; ntp++) {
                int sgB = wn * 4 + 2 * ntp + (lane >> 4);
                uint32_t b = bb + rB * 256 + ((sgB ^ (rB & 7)) << 4);
                unsigned t4[4];
                ldsm4t(b, t4);
                bf[2 * ntp][0] = t4[0]; bf[2 * ntp][1] = t4[1];
                bf[2 * ntp + 1][0] = t4[2]; bf[2 * ntp + 1][1] = t4[3];
            }
#pragma unroll
            for (int mt = 0; mt < 4; mt++)
#pragma unroll
                for (int nt = 0; nt < 4; nt++) {
                    mma_f16(acc[mt][nt], ah[mt], bf[nt]);
                    mma_f16(acc[mt][nt], al[mt], bf[nt]);
                }
        }
    }

    if (mode == 0) {
#pragma unroll
        for (int mt = 0; mt < 4; mt++) {
            int row = bm + wm * 64 + mt * 16 + g;
#pragma unroll
            for (int nt = 0; nt < 4; nt++) {
                int col = bn + wn * 32 + nt * 8 + 2 * t;
                if (col < N) {
                    *(float2*)&C[(size_t)row * N + col] =
                        make_float2(acc[mt][nt][0], acc[mt][nt][1]);
                    *(float2*)&C[(size_t)(row + 8) * N + col] =
                        make_float2(acc[mt][nt][2], acc[mt][nt][3]);
                }
            }
        }
    } else {
#pragma unroll
        for (int mt = 0; mt < 4; mt++) {
            int row = bm + wm * 64 + mt * 16 + g;
#pragma unroll
            for (int nt = 0; nt < 4; nt++) {
                int col = bn + wn * 32 + nt * 8 + 2 * t;
                *(unsigned*)(Ch + (size_t)row * N + col) =
                    packh2(acc[mt][nt][0], acc[mt][nt][1]);
                *(unsigned*)(Ch + (size_t)(row + 8) * N + col) =
                    packh2(acc[mt][nt][2], acc[mt][nt][3]);
            }
        }
    }
}

// ======================= RoPE-K =============================================
#define LOG2_10000_OVER_32 0.4152410118609203f

__global__ void rope_k_split(const float* __restrict__ src, int stride,
                             __half* __restrict__ kpe) {
    int w = (blockIdx.x * blockDim.x + threadIdx.x) >> 5;
    int lane = threadIdx.x & 31;
    if (w >= SQ) return;
    const float* base = src + (size_t)w * stride;
    float x0 = base[2 * lane];
    float x1 = base[2 * lane + 1];
    float invf = exp2f(-(float)lane * LOG2_10000_OVER_32);
    float ang = (float)w * invf;
    float sn, cs;
    sincosf(ang, &sn, &cs);
    kpe[(size_t)w * DRR + lane]      = __float2half(x0 * cs - x1 * sn);
    kpe[(size_t)w * DRR + 32 + lane] = __float2half(x1 * cs + x0 * sn);
}

// ======================= flash2: BM=64, occ 2, fp16 ========================
// 128 threads (4 warps x 16 rows). Single K buffer; co-resident CTA hides
// load latency. smem: Qh 0..24K, Ql 24K..48K, K 48K..72K, V 72K..88K.
#define OQH 0
#define OQL 24576
#define OKO 49152
#define OVO 73728
#define FL2_SMEM 90112

__global__ __launch_bounds__(128) void flash2(const float* __restrict__ q,
                                              const __half* __restrict__ kv,
                                              const __half* __restrict__ kpe,
                                              __half* __restrict__ Oh,
                                              __half* __restrict__ Ol) {
    extern __shared__ char smem[];
    const uint32_t sb = s2u(smem);
    const int tid = threadIdx.x, lane = tid & 31, warp = tid >> 5;
    const int g = lane >> 2, t = lane & 3;
    const int h = blockIdx.y;
    const int qb = gridDim.x - 1 - blockIdx.x;   // LPT: longest first
    const int q0 = qb * 64;
    const int r0 = warp * 16;
    const float scale = 0.07216878364870322f;

    auto load_KV = [&](int k0) {
        for (int i = tid; i < 64 * 24; i += 128) {
            int r = i / 24, sg = i % 24;
            uint32_t off = r * 384 + ((sg ^ (r & 7)) << 4);
            if (sg < 16) {
                cpa(sb + OKO + off, kv + (size_t)(k0 + r) * (HH * 256) + h * 256 + sg * 8);
            } else {
                cpa(sb + OKO + off, kpe + (size_t)(k0 + r) * DRR + (sg - 16) * 8);
            }
        }
        for (int i = tid; i < 64 * 16; i += 128) {
            int r = i / 16, sg = i % 16;
            uint32_t off = r * 256 + ((sg ^ (r & 7)) << 4);
            cpa(sb + OVO + off, kv + (size_t)(k0 + r) * (HH * 256) + h * 256 + DNN + sg * 8);
        }
        CP_COMMIT;
    };

    // kick off first K/V load, then do Q while it flies
    load_KV(0);

    // ---- Q load with fused RoPE + hi/lo split ----
    for (int i = tid; i < 64 * 24; i += 128) {
        int r = i / 24, sg = i % 24;
        int qrow = q0 + r;
        const float* qr = q + (size_t)qrow * (HH * DQQ) + h * DQQ;
        float f[8];
        if (sg < 16) {
            *(float4*)&f[0] = *(const float4*)(qr + sg * 8);
            *(float4*)&f[4] = *(const float4*)(qr + sg * 8 + 4);
        } else {
            int u_base = (sg - 16) * 8;
            int j_base = u_base & 31;
            float f2[16];
            const float* pe = qr + DNN + 2 * j_base;
#pragma unroll
            for (int v = 0; v < 4; v++) *(float4*)&f2[4 * v] = *(const float4*)(pe + 4 * v);
#pragma unroll
            for (int j2 = 0; j2 < 8; j2++) {
                int j = j_base + j2;
                float x0 = f2[2 * j2], x1 = f2[2 * j2 + 1];
                float invf = exp2f(-(float)j * LOG2_10000_OVER_32);
                float sn, cs;
                sincosf((float)qrow * invf, &sn, &cs);
                f[j2] = (u_base < 32) ? (x0 * cs - x1 * sn) : (x1 * cs + x0 * sn);
            }
        }
        uint4 hv, lv;
        split8(f, hv, lv);
        uint32_t off = r * 384 + ((sg ^ (r & 7)) << 4);
        *(uint4*)(smem + OQH + off) = hv;
        *(uint4*)(smem + OQL + off) = lv;
    }

    float m0 = -1e30f, m1 = -1e30f, l0 = 0.f, l1 = 0.f;
    float oacc[16][4];
#pragma unroll
    for (int nv = 0; nv < 16; nv++)
#pragma unroll
        for (int k = 0; k < 4; k++) oacc[nv][k] = 0.f;

    const int nkb = qb + 1;
    for (int kb = 0; kb < nkb; kb++) {
        const int k0 = kb * 64;
        CP_WAIT0;
        __syncthreads();

        // S = Q @ K^T
        float sacc[8][4];
#pragma unroll
        for (int nt = 0; nt < 8; nt++)
#pragma unroll
            for (int k = 0; k < 4; k++) sacc[nt][k] = 0.f;

        const int lr = (lane & 7) + 8 * ((lane >> 3) & 1);
#pragma unroll
        for (int kk = 0; kk < 192; kk += 16) {
            unsigned ah[4], al[4];
            int rowA = r0 + lr;
            int sgA = (kk >> 3) + (lane >> 4);
            uint32_t a = sb + OQH + rowA * 384 + ((sgA ^ (rowA & 7)) << 4);
            ldsm4(a, ah);
            ldsm4(a + (OQL - OQH), al);
            int sgB = (kk >> 3) + ((lane >> 3) & 1);
#pragma unroll
            for (int ntp = 0; ntp < 4; ntp++) {
                int rB = (2 * ntp + (lane >> 4)) * 8 + (lane & 7);
                uint32_t b = sb + OKO + rB * 384 + ((sgB ^ (rB & 7)) << 4);
                unsigned b4[4];
                ldsm4(b, b4);
                mma_f16(sacc[2 * ntp],     ah, &b4[0]);
                mma_f16(sacc[2 * ntp],     al, &b4[0]);
                mma_f16(sacc[2 * ntp + 1], ah, &b4[2]);
                mma_f16(sacc[2 * ntp + 1], al, &b4[2]);
            }
        }

        // mask + online softmax
        const int qi0 = q0 + r0 + g;
        const int qi1 = qi0 + 8;
        const bool full = (k0 + 63 <= q0 + r0);
        float mx0 = -1e30f, mx1 = -1e30f;
#pragma unroll
        for (int nt = 0; nt < 8; nt++) {
            int c = k0 + nt * 8 + 2 * t;
            float s00 = sacc[nt][0] * scale, s01 = sacc[nt][1] * scale;
            float s10 = sacc[nt][2] * scale, s11 = sacc[nt][3] * scale;
            if (!full) {
                if (c > qi0)     s00 = -1e30f;
                if (c + 1 > qi0) s01 = -1e30f;
                if (c > qi1)     s10 = -1e30f;
                if (c + 1 > qi1) s11 = -1e30f;
            }
            sacc[nt][0] = s00; sacc[nt][1] = s01;
            sacc[nt][2] = s10; sacc[nt][3] = s11;
            mx0 = fmaxf(mx0, fmaxf(s00, s01));
            mx1 = fmaxf(mx1, fmaxf(s10, s11));
        }
        mx0 = fmaxf(mx0, __shfl_xor_sync(0xffffffffu, mx0, 1));
        mx0 = fmaxf(mx0, __shfl_xor_sync(0xffffffffu, mx0, 2));
        mx1 = fmaxf(mx1, __shfl_xor_sync(0xffffffffu, mx1, 1));
        mx1 = fmaxf(mx1, __shfl_xor_sync(0xffffffffu, mx1, 2));

        float mn0 = fmaxf(m0, mx0), mn1 = fmaxf(m1, mx1);
        float a0 = __expf(m0 - mn0), a1 = __expf(m1 - mn1);
        float s0 = 0.f, s1 = 0.f;
#pragma unroll
        for (int nt = 0; nt < 8; nt++) {
            float p00 = __expf(sacc[nt][0] - mn0);
            float p01 = __expf(sacc[nt][1] - mn0);
            float p10 = __expf(sacc[nt][2] - mn1);
            float p11 = __expf(sacc[nt][3] - mn1);
            sacc[nt][0] = p00; sacc[nt][1] = p01;
            sacc[nt][2] = p10; sacc[nt][3] = p11;
            s0 += p00 + p01;
            s1 += p10 + p11;
        }
        s0 += __shfl_xor_sync(0xffffffffu, s0, 1);
        s0 += __shfl_xor_sync(0xffffffffu, s0, 2);
        s1 += __shfl_xor_sync(0xffffffffu, s1, 1);
        s1 += __shfl_xor_sync(0xffffffffu, s1, 2);
        l0 = l0 * a0 + s0;
        l1 = l1 * a1 + s1;
        m0 = mn0; m1 = mn1;
#pragma unroll
        for (int nv = 0; nv < 16; nv++) {
            oacc[nv][0] *= a0; oacc[nv][1] *= a0;
            oacc[nv][2] *= a1; oacc[nv][3] *= a1;
        }

        // O += P @ V  (P hi/lo, V single)
        const int lrv = (lane & 7) + 8 * ((lane >> 3) & 1);
#pragma unroll
        for (int u = 0; u < 4; u++) {
            unsigned pah[4], pal[4];
            packsplit(sacc[2 * u][0],     sacc[2 * u][1],     pah[0], pal[0]);
            packsplit(sacc[2 * u][2],     sacc[2 * u][3],     pah[1], pal[1]);
            packsplit(sacc[2 * u + 1][0], sacc[2 * u + 1][1], pah[2], pal[2]);
            packsplit(sacc[2 * u + 1][2], sacc[2 * u + 1][3], pah[3], pal[3]);
            int rV = u * 16 + lrv;
#pragma unroll
            for (int nvp = 0; nvp < 8; nvp++) {
                int nv0 = 2 * nvp;
                uint32_t a = sb + OVO + rV * 256 +
                             (((nv0 + (lane >> 4)) ^ (rV & 7)) << 4);
                unsigned bv4[4];
                ldsm4t(a, bv4);
                mma_f16(oacc[nv0],     pah, &bv4[0]);
                mma_f16(oacc[nv0],     pal, &bv4[0]);
                mma_f16(oacc[nv0 + 1], pah, &bv4[2]);
                mma_f16(oacc[nv0 + 1], pal, &bv4[2]);
            }
        }

        // launch next K/V load (buffers free: all reads this iter done)
        if (kb + 1 < nkb) {
            __syncthreads();
            load_KV(k0 + 64);
        }
    }

    // epilogue: normalize + hi/lo split (A side of out-proj)
    float i0 = 1.f / l0, i1 = 1.f / l1;
    int row0 = q0 + r0 + g;
#pragma unroll
    for (int nv = 0; nv < 16; nv++) {
        int col = h * DVV + nv * 8 + 2 * t;
        unsigned hw, lw;
        packsplit(oacc[nv][0] * i0, oacc[nv][1] * i0, hw, lw);
        *(unsigned*)(Oh + (size_t)row0 * (HH * DVV) + col) = hw;
        *(unsigned*)(Ol + (size_t)row0 * (HH * DVV) + col) = lw;
        packsplit(oacc[nv][2] * i1, oacc[nv][3] * i1, hw, lw);
        *(unsigned*)(Oh + (size_t)(row0 + 8) * (HH * DVV) + col) = hw;
        *(unsigned*)(Ol + (size_t)(row0 + 8) * (HH * DVV) + col) = lw;
    }
}

// ======================= launch =======================
extern "C" void kernel_launch(void* const* d_in, const int* in_sizes, int n_in,
                              void* d_out, int out_size) {
    const float* x       = (const float*)d_in[0];
    const float* w_q_a   = (const float*)d_in[1];
    const float* q_a_ln  = (const float*)d_in[2];
    const float* w_q_b   = (const float*)d_in[3];
    const float* w_kv_a  = (const float*)d_in[4];
    const float* kv_a_ln = (const float*)d_in[5];
    const float* w_kv_b  = (const float*)d_in[6];
    const float* w_out   = (const float*)d_in[7];
    float* out = (float*)d_out;

    float *c1, *qbuf;
    __half *Ah, *Al, *B1, *B2, *B3, *BO, *A2h, *A2l, *kv, *kpe;
    cudaGetSymbolAddress((void**)&c1,   g_c1);
    cudaGetSymbolAddress((void**)&qbuf, g_q);
    cudaGetSymbolAddress((void**)&Ah,   g_Ah);
    cudaGetSymbolAddress((void**)&Al,   g_Al);
    cudaGetSymbolAddress((void**)&B1,   g_B1);
    cudaGetSymbolAddress((void**)&B2,   g_B2);
    cudaGetSymbolAddress((void**)&B3,   g_B3);
    cudaGetSymbolAddress((void**)&BO,   g_BO);
    cudaGetSymbolAddress((void**)&A2h,  g_A2h);
    cudaGetSymbolAddress((void**)&A2l,  g_A2l);
    cudaGetSymbolAddress((void**)&kv,   g_kv);
    cudaGetSymbolAddress((void**)&kpe,  g_kpe);

    cudaFuncSetAttribute(bgemm2, cudaFuncAttributeMaxDynamicSharedMemorySize, BG_SMEM);
    cudaFuncSetAttribute(flash2, cudaFuncAttributeMaxDynamicSharedMemorySize, FL2_SMEM);

    cudaStream_t s2;
    cudaStreamCreateWithFlags(&s2, cudaStreamNonBlocking);
    cudaEvent_t eF0, eJ0, eF1, eJ1;
    cudaEventCreateWithFlags(&eF0, cudaEventDisableTiming);
    cudaEventCreateWithFlags(&eJ0, cudaEventDisableTiming);
    cudaEventCreateWithFlags(&eF1, cudaEventDisableTiming);
    cudaEventCreateWithFlags(&eJ1, cudaEventDisableTiming);

    dim3 blk(256);

    // ---- main: x split, fork weight convs to s2 ----
    conv_split<<<(SQ * EE / 8 + 255) / 256, blk>>>(x, Ah, Al, SQ * EE);
    cudaEventRecord(eF0, 0);
    cudaStreamWaitEvent(s2, eF0, 0);
    conv_single<<<(QLR * HH * DQQ / 8 + 255) / 256, blk, 0, s2>>>(w_q_b, B3, QLR * HH * DQQ);
    conv_single<<<(KLR * HH * 256 / 8 + 255) / 256, blk, 0, s2>>>(w_kv_b, B2, KLR * HH * 256);
    cudaEventRecord(eJ0, s2);

    // ---- main: gemm1 weights + gemm1 ----
    conv_singleN<<<(EE * QLR / 8 + 255) / 256, blk>>>(w_q_a, B1, QLR, 0, N1C, EE * QLR);
    conv_singleN<<<(EE * (KLR + DRR) / 8 + 255) / 256, blk>>>(
        w_kv_a, B1, KLR + DRR, QLR, N1C, EE * (KLR + DRR));
    bgemm2<<<dim3(N1C / 128, SQ / 128), blk, BG_SMEM>>>(
        Ah, Al, B1, c1, nullptr, N1C, EE, 0);

    rope_k_split<<<(SQ * 32 + 255) / 256, blk>>>(c1 + QLR + KLR, N1C, kpe);

    rmsnorm_split<<<SQ, blk>>>(c1, q_a_ln, Ah, Al, QLR, N1C);
    rmsnorm_split<<<SQ, blk>>>(c1 + QLR, kv_a_ln, A2h, A2l, KLR, N1C);

    // join weight convs; fork kv gemm to s2
    cudaStreamWaitEvent(0, eJ0, 0);
    cudaEventRecord(eF1, 0);
    cudaStreamWaitEvent(s2, eF1, 0);
    bgemm2<<<dim3((HH * 256) / 128, SQ / 128), blk, BG_SMEM, s2>>>(
        A2h, A2l, B2, nullptr, kv, HH * 256, KLR, 1);
    cudaEventRecord(eJ1, s2);

    // main: q = qa_n @ w_q_b (concurrent)
    bgemm2<<<dim3((HH * DQQ) / 128, SQ / 128), blk, BG_SMEM>>>(
        Ah, Al, B3, qbuf, nullptr, HH * DQQ, QLR, 0);

    // main: w_out single split
    conv_single<<<(HH * DVV * EE / 8 + 255) / 256, blk>>>(w_out, BO, HH * DVV * EE);

    // join kv gemm, attention (BM=64, 128 threads, occ 2)
    cudaStreamWaitEvent(0, eJ1, 0);
    flash2<<<dim3(SQ / 64, HH), dim3(128), FL2_SMEM>>>(qbuf, kv, kpe, Ah, Al);

    // out = o @ w_out
    bgemm2<<<dim3(EE / 128, SQ / 128), blk, BG_SMEM>>>(
        Ah, Al, BO, out, nullptr, EE, HH * DVV, 0);
}